// round 8
// baseline (speedup 1.0000x reference)
#include <cuda_runtime.h>
#include <cuda_bf16.h>
#include <cstdint>

#define N_PIX 4096
#define BATCH 4
#define CH    256
#define DQK   32

typedef unsigned long long u64;
typedef unsigned int u32;

// ---------------- scratch (device globals) ------------------------------------------
__device__ __nv_bfloat16 g_qh[(size_t)BATCH * N_PIX * DQK];  // Q hi [b][n][32]
__device__ __nv_bfloat16 g_ql[(size_t)BATCH * N_PIX * DQK];  // Q lo
__device__ __nv_bfloat16 g_kh[(size_t)BATCH * N_PIX * DQK];  // K hi [b][m][32]
__device__ __nv_bfloat16 g_kl[(size_t)BATCH * N_PIX * DQK];  // K lo
__device__ __nv_bfloat16 g_vh[(size_t)BATCH * CH * N_PIX];   // V hi [b][d][m]
__device__ __nv_bfloat16 g_vl[(size_t)BATCH * CH * N_PIX];   // V lo

// ---------------- f32x2 helpers ------------------------------------------------------
__device__ __forceinline__ u64 fma2(u64 a, u64 b, u64 c) {
    u64 d;
    asm("fma.rn.f32x2 %0, %1, %2, %3;" : "=l"(d) : "l"(a), "l"(b), "l"(c));
    return d;
}
__device__ __forceinline__ u64 pack2(float x, float y) {
    u64 r;
    asm("mov.b64 %0, {%1, %2};" : "=l"(r) : "f"(x), "f"(y));
    return r;
}
__device__ __forceinline__ float2 unpack2(u64 v) {
    float2 r;
    asm("mov.b64 {%0, %1}, %2;" : "=f"(r.x), "=f"(r.y) : "l"(v));
    return r;
}

// ---------------- split-bf16 helpers --------------------------------------------------
__device__ __forceinline__ void split2(float a, float b, u32& hi, u32& lo) {
    __nv_bfloat162 h = __floats2bfloat162_rn(a, b);
    u32 hraw = *(const u32*)&h;
    float ha = __uint_as_float(hraw << 16);
    float hb = __uint_as_float(hraw & 0xFFFF0000u);
    __nv_bfloat162 l = __floats2bfloat162_rn(a - ha, b - hb);
    hi = hraw;
    lo = *(const u32*)&l;
}
__device__ __forceinline__ void split_store4(__nv_bfloat16* hp, __nv_bfloat16* lp,
                                             float f0, float f1, float f2, float f3)
{
    u32 h0, l0, h1, l1;
    split2(f0, f1, h0, l0);
    split2(f2, f3, h1, l1);
    *(uint2*)hp = make_uint2(h0, h1);
    *(uint2*)lp = make_uint2(l0, l1);
}

// ---------------- smem / async / mma helpers ----------------------------------------
__device__ __forceinline__ u32 smem_u32(const void* p) {
    u32 a;
    asm("{ .reg .u64 t; cvta.to.shared.u64 t, %1; cvt.u32.u64 %0, t; }" : "=r"(a) : "l"(p));
    return a;
}
__device__ __forceinline__ void cp16(u32 d, const void* s) {
    asm volatile("cp.async.cg.shared.global [%0], [%1], 16;" :: "r"(d), "l"(s));
}
#define CP_COMMIT() asm volatile("cp.async.commit_group;" ::: "memory")
#define CP_WAIT0()  asm volatile("cp.async.wait_group 0;" ::: "memory")

// bulk async copy: global -> shared, completion via mbarrier tx-bytes
__device__ __forceinline__ void bulkcp(u32 dst, const void* src, u32 bytes, u32 mbar) {
    asm volatile(
        "cp.async.bulk.shared::cluster.global.mbarrier::complete_tx::bytes "
        "[%0], [%1], %2, [%3];"
        :: "r"(dst), "l"(src), "r"(bytes), "r"(mbar) : "memory");
}
#define MBAR_INIT(addr, cnt) \
    asm volatile("mbarrier.init.shared.b64 [%0], %1;" :: "r"(addr), "r"(cnt) : "memory")
#define MBAR_EXPECT(addr, bytes) \
    asm volatile("mbarrier.arrive.expect_tx.shared.b64 _, [%0], %1;" \
                 :: "r"(addr), "r"(bytes) : "memory")
#define FENCE_ASYNC() asm volatile("fence.proxy.async.shared::cta;" ::: "memory")

__device__ __forceinline__ void mbar_wait(u32 addr, u32 parity) {
    asm volatile(
        "{\n\t.reg .pred P;\n"
        "W%=:\n\t"
        "mbarrier.try_wait.parity.acquire.cta.shared::cta.b64 P, [%0], %1, 0x989680;\n\t"
        "@P bra D%=;\n\t"
        "bra W%=;\n"
        "D%=:\n\t}"
        :: "r"(addr), "r"(parity) : "memory");
}

__device__ __forceinline__ void ldm4(u32 addr, u32& r0, u32& r1, u32& r2, u32& r3) {
    asm volatile("ldmatrix.sync.aligned.m8n8.x4.shared.b16 {%0,%1,%2,%3}, [%4];"
                 : "=r"(r0), "=r"(r1), "=r"(r2), "=r"(r3) : "r"(addr));
}
__device__ __forceinline__ void mma16816(float* c, const u32* a, u32 b0, u32 b1) {
    asm volatile(
        "mma.sync.aligned.m16n8k16.row.col.f32.bf16.bf16.f32 "
        "{%0,%1,%2,%3}, {%4,%5,%6,%7}, {%8,%9}, {%0,%1,%2,%3};"
        : "+f"(c[0]), "+f"(c[1]), "+f"(c[2]), "+f"(c[3])
        : "r"(a[0]), "r"(a[1]), "r"(a[2]), "r"(a[3]), "r"(b0), "r"(b1));
}

// ================== kernel 1: q/k projection (128 px/CTA, split-bf16 out) ==========
__global__ void __launch_bounds__(256) proj_qk_kernel(
    const float* __restrict__ x,
    const float* __restrict__ Wq, const float* __restrict__ bq,
    const float* __restrict__ Wk, const float* __restrict__ bk)
{
    __shared__ float sX[32 * 132];
    __shared__ float sW[32 * 68];

    const int tid = threadIdx.x;
    const int g = tid & 31;          // 4-pixel group
    const int h = tid >> 5;          // 0..7: h<4 -> q, else k
    const int b = blockIdx.y;
    const int n0 = blockIdx.x * 128;
    const bool isq = (h < 4);
    const int dbase = (h & 3) * 8;
    const int woff = (isq ? 0 : 32) + dbase;

    u64 acc[8][2];
#pragma unroll
    for (int i = 0; i < 8; i++) { acc[i][0] = 0; acc[i][1] = 0; }

    for (int c0 = 0; c0 < CH; c0 += 32) {
        __syncthreads();
#pragma unroll
        for (int pass = 0; pass < 4; ++pass) {
            int cc = h + pass * 8;
            const float* src = x + ((size_t)b * CH + c0 + cc) * N_PIX + n0 + g * 4;
            *(float4*)(sX + cc * 132 + g * 4) = *(const float4*)src;
        }
        {
            int d = tid & 31;
            int c4 = (tid >> 5) * 4;
            float4 wq4 = *(const float4*)(Wq + d * CH + c0 + c4);
            float4 wk4 = *(const float4*)(Wk + d * CH + c0 + c4);
            sW[(c4 + 0) * 68 + d] = wq4.x; sW[(c4 + 1) * 68 + d] = wq4.y;
            sW[(c4 + 2) * 68 + d] = wq4.z; sW[(c4 + 3) * 68 + d] = wq4.w;
            sW[(c4 + 0) * 68 + 32 + d] = wk4.x; sW[(c4 + 1) * 68 + 32 + d] = wk4.y;
            sW[(c4 + 2) * 68 + 32 + d] = wk4.z; sW[(c4 + 3) * 68 + 32 + d] = wk4.w;
        }
        __syncthreads();

#pragma unroll 8
        for (int cc = 0; cc < 32; ++cc) {
            float4 xa = *(const float4*)(sX + cc * 132 + g * 4);
            u64 xp0 = pack2(xa.x, xa.y), xp1 = pack2(xa.z, xa.w);
            const float* wp = sW + cc * 68 + woff;
            float4 w0 = *(const float4*)wp;
            float4 w1 = *(const float4*)(wp + 4);
            float wv[8] = {w0.x, w0.y, w0.z, w0.w, w1.x, w1.y, w1.z, w1.w};
#pragma unroll
            for (int i = 0; i < 8; i++) {
                u64 wd = pack2(wv[i], wv[i]);
                acc[i][0] = fma2(wd, xp0, acc[i][0]);
                acc[i][1] = fma2(wd, xp1, acc[i][1]);
            }
        }
    }

    const float* bias = isq ? bq : bk;
    float bb[8];
#pragma unroll
    for (int i = 0; i < 8; i++) bb[i] = bias[dbase + i];
    __nv_bfloat16* oh = (isq ? g_qh : g_kh) + ((size_t)b * N_PIX + n0 + g * 4) * DQK + dbase;
    __nv_bfloat16* ol = (isq ? g_ql : g_kl) + ((size_t)b * N_PIX + n0 + g * 4) * DQK + dbase;
#pragma unroll
    for (int j = 0; j < 4; j++) {
        float v[8];
#pragma unroll
        for (int i = 0; i < 8; i++) {
            float2 t = unpack2(acc[i][j >> 1]);
            v[i] = ((j & 1) ? t.y : t.x) + bb[i];
        }
        u32 hh[4], ll[4];
        split2(v[0], v[1], hh[0], ll[0]);
        split2(v[2], v[3], hh[1], ll[1]);
        split2(v[4], v[5], hh[2], ll[2]);
        split2(v[6], v[7], hh[3], ll[3]);
        *(uint4*)(oh + (size_t)j * DQK) = make_uint4(hh[0], hh[1], hh[2], hh[3]);
        *(uint4*)(ol + (size_t)j * DQK) = make_uint4(ll[0], ll[1], ll[2], ll[3]);
    }
}

// ================== kernel 2: v projection (writes split-bf16 V) ===================
__global__ void __launch_bounds__(256) proj_v_kernel(
    const float* __restrict__ x, const float* __restrict__ Wv, const float* __restrict__ bv)
{
    __shared__ float sA[32][68];
    __shared__ float sB[32][68];

    int b  = blockIdx.z;
    int n0 = blockIdx.x * 64;
    int d0 = blockIdx.y * 64;
    int tx = threadIdx.x, ty = threadIdx.y, tid = ty * 16 + tx;

    float acc[4][4] = {};

    for (int c0 = 0; c0 < CH; c0 += 32) {
        for (int idx = tid; idx < 512; idx += 256) {
            int r = idx >> 3, q = idx & 7;
            float4 w = *(const float4*)(Wv + (size_t)(d0 + r) * CH + c0 + q * 4);
            sA[q * 4 + 0][r] = w.x; sA[q * 4 + 1][r] = w.y;
            sA[q * 4 + 2][r] = w.z; sA[q * 4 + 3][r] = w.w;

            int r2 = idx >> 4, q2 = idx & 15;
            float4 xv = *(const float4*)(x + ((size_t)b * CH + c0 + r2) * N_PIX + n0 + q2 * 4);
            *(float4*)&sB[r2][q2 * 4] = xv;
        }
        __syncthreads();

#pragma unroll
        for (int k = 0; k < 32; k++) {
            float4 a4 = *(const float4*)&sA[k][ty * 4];
            float4 b4 = *(const float4*)&sB[k][tx * 4];
            float av[4] = {a4.x, a4.y, a4.z, a4.w};
            float bw[4] = {b4.x, b4.y, b4.z, b4.w};
#pragma unroll
            for (int i = 0; i < 4; i++)
#pragma unroll
                for (int j = 0; j < 4; j++)
                    acc[i][j] += av[i] * bw[j];
        }
        __syncthreads();
    }

#pragma unroll
    for (int i = 0; i < 4; i++) {
        int d = d0 + ty * 4 + i;
        float bias = bv[d];
        size_t base = ((size_t)b * CH + d) * N_PIX + n0 + tx * 4;
        split_store4(g_vh + base, g_vl + base,
                     acc[i][0] + bias, acc[i][1] + bias,
                     acc[i][2] + bias, acc[i][3] + bias);
    }
}

// ================== kernel 3: fused attention, bulk-copy pipeline ==================
#define FA_QH   0u           // 128 x 40 halves
#define FA_QL   10240u
#define FA_K    20480u       // 2 bufs x (hi 10240 + lo 10240); row pitch 40 halves
#define FA_KBUF 20480u
#define FA_KLO  10240u
#define FA_VH   61440u       // 128 x 136 halves (272 B pitch)
#define FA_VL   96256u
#define FA_PH   131072u
#define FA_PL   165888u
#define FA_SROW 200704u
#define FA_SINV 201216u
#define FA_MBV  201728u
#define FA_MBK0 201744u
#define FA_MBK1 201760u
#define FA_SMEM 201792u

#define V_BYTES 65536u
#define K_BYTES 16384u

__global__ void __launch_bounds__(256, 1) fused_attn_kernel(
    const float* __restrict__ x, float* __restrict__ out)
{
    extern __shared__ char sm[];
    const u32 S = smem_u32(sm);

    const int tid = threadIdx.x;
    const int w = tid >> 5, lane = tid & 31;
    const int b  = blockIdx.z;
    const int n0 = blockIdx.x * 128;
    const int d0 = blockIdx.y * 128;

    const __nv_bfloat16* qh = g_qh + ((size_t)b * N_PIX + n0) * DQK;
    const __nv_bfloat16* ql = g_ql + ((size_t)b * N_PIX + n0) * DQK;
    const __nv_bfloat16* kh = g_kh + (size_t)b * N_PIX * DQK;
    const __nv_bfloat16* kl = g_kl + (size_t)b * N_PIX * DQK;
    const __nv_bfloat16* vh = g_vh + ((size_t)b * CH + d0) * N_PIX;
    const __nv_bfloat16* vl = g_vl + ((size_t)b * CH + d0) * N_PIX;

    // each of the 256 threads issues exactly one V-row op and one K-row op
    const int brmat = tid >> 7;       // 0 = hi, 1 = lo
    const int brrow = tid & 127;

    auto bulk_v = [&](int m0) {
        const __nv_bfloat16* src = (brmat ? vl : vh) + (size_t)brrow * N_PIX + m0;
        u32 dst = S + (brmat ? FA_VL : FA_VH) + (u32)brrow * 272u;
        bulkcp(dst, src, 256u, S + FA_MBV);
    };
    auto bulk_k = [&](int t2, u32 kbuf, u32 mbar) {
        const __nv_bfloat16* src = (brmat ? kl : kh) + ((size_t)t2 * 128 + brrow) * DQK;
        u32 dst = kbuf + (u32)brmat * FA_KLO + (u32)brrow * 80u;
        bulkcp(dst, src, 64u, mbar);
    };
    auto load_q = [&]() {
#pragma unroll
        for (int j = 0; j < 4; ++j) {
            int idx = tid + j * 256;
            int mat = idx >> 9;
            int within = idx & 511;
            int row = within >> 2, c = within & 3;
            const __nv_bfloat16* src = (mat ? ql : qh) + (size_t)row * DQK + c * 8;
            cp16(S + (u32)mat * 10240u + (u32)(row * 40 + c * 8) * 2, src);
        }
    };

    // ---- prologue ----
    if (tid == 0) {
        MBAR_INIT(S + FA_MBV, 1);
        MBAR_INIT(S + FA_MBK0, 1);
        MBAR_INIT(S + FA_MBK1, 1);
    }
    __syncthreads();
    if (tid == 0)  MBAR_EXPECT(S + FA_MBV, V_BYTES);
    if (tid == 32) MBAR_EXPECT(S + FA_MBK0, K_BYTES);
    if (tid == 64) MBAR_EXPECT(S + FA_MBK1, K_BYTES);
    __syncthreads();
    FENCE_ASYNC();
    load_q();
    CP_COMMIT();
    bulk_v(0);
    bulk_k(0, S + FA_K, S + FA_MBK0);
    bulk_k(1, S + FA_K + FA_KBUF, S + FA_MBK1);
    CP_WAIT0();     // Q ready (bulk completion tracked by mbarriers)
    __syncthreads();

    float accO[16][4];
#pragma unroll
    for (int i = 0; i < 16; i++)
#pragma unroll
        for (int q = 0; q < 4; q++) accO[i][q] = 0.f;
    float rs0 = 0.f, rs1 = 0.f;

    const int arow = w * 16 + (lane & 15);
    const int acol = (lane >> 4) << 3;
    const int brow = (lane & 7) + ((lane >> 4) & 1) * 8;
    const int bcol = ((lane >> 3) & 1) * 8;

    const int NT = N_PIX / 128;  // 32 m-tiles
    for (int t = 0; t < NT; ++t) {
        // K(t) ready?
        mbar_wait(S + ((t & 1) ? FA_MBK1 : FA_MBK0), (u32)((t >> 1) & 1));

        // ---- E phase ----
        const u32 kb = S + FA_K + (u32)(t & 1) * FA_KBUF;
        float accE[16][4];
#pragma unroll
        for (int i = 0; i < 16; i++)
#pragma unroll
            for (int q = 0; q < 4; q++) accE[i][q] = 0.f;

#pragma unroll
        for (int kk = 0; kk < 32; kk += 16) {
            u32 ah[4], al[4];
            u32 ao = (u32)(arow * 40 + acol + kk) * 2;
            ldm4(S + FA_QH + ao, ah[0], ah[1], ah[2], ah[3]);
            ldm4(S + FA_QL + ao, al[0], al[1], al[2], al[3]);
#pragma unroll
            for (int nf = 0; nf < 8; nf++) {
                u32 bo = (u32)((nf * 16 + brow) * 40 + bcol + kk) * 2;
                u32 bh[4], bl[4];
                ldm4(kb + bo, bh[0], bh[1], bh[2], bh[3]);
                ldm4(kb + FA_KLO + bo, bl[0], bl[1], bl[2], bl[3]);
                mma16816(accE[nf * 2],     ah, bh[0], bh[1]);
                mma16816(accE[nf * 2],     ah, bl[0], bl[1]);
                mma16816(accE[nf * 2],     al, bh[0], bh[1]);
                mma16816(accE[nf * 2 + 1], ah, bh[2], bh[3]);
                mma16816(accE[nf * 2 + 1], ah, bl[2], bl[3]);
                mma16816(accE[nf * 2 + 1], al, bh[2], bh[3]);
            }
        }

        // ---- exp + rowsum + split-bf16 store to P smem ----
        {
            const int prow = w * 16 + (lane >> 2);
            const int pcol = 2 * (lane & 3);
#pragma unroll
            for (int nf = 0; nf < 16; nf++) {
                float e0 = __expf(accE[nf][0]);
                float e1 = __expf(accE[nf][1]);
                float e2 = __expf(accE[nf][2]);
                float e3 = __expf(accE[nf][3]);
                rs0 += e0 + e1;
                rs1 += e2 + e3;
                u32 hi0, lo0, hi1, lo1;
                split2(e0, e1, hi0, lo0);
                split2(e2, e3, hi1, lo1);
                u32 off0 = (u32)(prow * 136 + nf * 8 + pcol) * 2;
                u32 off1 = off0 + 8u * 136u * 2u;
                *(u32*)(sm + FA_PH + off0) = hi0;
                *(u32*)(sm + FA_PL + off0) = lo0;
                *(u32*)(sm + FA_PH + off1) = hi1;
                *(u32*)(sm + FA_PL + off1) = lo1;
            }
        }
        __syncthreads();

        // V(t) ready?
        mbar_wait(S + FA_MBV, (u32)(t & 1));

        // ---- PV phase ----
#pragma unroll
        for (int ks = 0; ks < 8; ks++) {
            u32 ah[4], al[4];
            u32 ao = (u32)(arow * 136 + acol + ks * 16) * 2;
            ldm4(S + FA_VH + ao, ah[0], ah[1], ah[2], ah[3]);
            ldm4(S + FA_VL + ao, al[0], al[1], al[2], al[3]);
#pragma unroll
            for (int nf = 0; nf < 8; nf++) {
                u32 bo = (u32)((nf * 16 + brow) * 136 + bcol + ks * 16) * 2;
                u32 bh[4], bl[4];
                ldm4(S + FA_PH + bo, bh[0], bh[1], bh[2], bh[3]);
                ldm4(S + FA_PL + bo, bl[0], bl[1], bl[2], bl[3]);
                mma16816(accO[nf * 2],     ah, bh[0], bh[1]);
                mma16816(accO[nf * 2],     ah, bl[0], bl[1]);
                mma16816(accO[nf * 2],     al, bh[0], bh[1]);
                mma16816(accO[nf * 2 + 1], ah, bh[2], bh[3]);
                mma16816(accO[nf * 2 + 1], ah, bl[2], bl[3]);
                mma16816(accO[nf * 2 + 1], al, bh[2], bh[3]);
            }
        }

        // arm barriers for next loads BEFORE the sync that releases the buffers
        if (tid == 0 && t + 1 < NT)  MBAR_EXPECT(S + FA_MBV, V_BYTES);
        if (tid == 32 && t + 2 < NT)
            MBAR_EXPECT(S + ((t & 1) ? FA_MBK1 : FA_MBK0), K_BYTES);
        __syncthreads();     // all V/P reads done; expects visible

        FENCE_ASYNC();
        if (t + 1 < NT) bulk_v((t + 1) * 128);
        if (t + 2 < NT)
            bulk_k(t + 2, S + FA_K + (u32)(t & 1) * FA_KBUF,
                   S + ((t & 1) ? FA_MBK1 : FA_MBK0));
    }

    // ---- row sums: quad-reduce, then -> 1/sum ----
    rs0 += __shfl_xor_sync(0xffffffffu, rs0, 1);
    rs0 += __shfl_xor_sync(0xffffffffu, rs0, 2);
    rs1 += __shfl_xor_sync(0xffffffffu, rs1, 1);
    rs1 += __shfl_xor_sync(0xffffffffu, rs1, 2);
    if ((lane & 3) == 0) {
        ((float*)(sm + FA_SROW))[w * 16 + (lane >> 2)] = rs0;
        ((float*)(sm + FA_SROW))[w * 16 + (lane >> 2) + 8] = rs1;
    }
    __syncthreads();
    if (tid < 128)
        ((float*)(sm + FA_SINV))[tid] = 1.0f / ((float*)(sm + FA_SROW))[tid];
    __syncthreads();

    // ---- epilogue: out = accO * rinv[n] + x ----
    const float* sinv = (const float*)(sm + FA_SINV);
    const int er = lane >> 2;
    const int ec = 2 * (lane & 3);
#pragma unroll
    for (int nf = 0; nf < 16; nf++) {
        const int n = nf * 8 + ec;
        float2 rv = *(const float2*)(sinv + n);
        const int d = d0 + w * 16 + er;
        size_t o1 = ((size_t)b * CH + d) * N_PIX + n0 + n;
        size_t o2 = o1 + (size_t)8 * N_PIX;
        float2 x1 = *(const float2*)(x + o1);
        float2 x2 = *(const float2*)(x + o2);
        *(float2*)(out + o1) = make_float2(accO[nf][0] * rv.x + x1.x,
                                           accO[nf][1] * rv.y + x1.y);
        *(float2*)(out + o2) = make_float2(accO[nf][2] * rv.x + x2.x,
                                           accO[nf][3] * rv.y + x2.y);
    }
}

// ================== launch =========================================================
extern "C" void kernel_launch(void* const* d_in, const int* in_sizes, int n_in,
                              void* d_out, int out_size)
{
    (void)in_sizes; (void)n_in; (void)out_size;
    const float* x  = (const float*)d_in[0];
    const float* Wq = (const float*)d_in[1];
    const float* bq = (const float*)d_in[2];
    const float* Wk = (const float*)d_in[3];
    const float* bk = (const float*)d_in[4];
    const float* Wv = (const float*)d_in[5];
    const float* bv = (const float*)d_in[6];
    float* out = (float*)d_out;

    static int smem_set = 0;
    if (!smem_set) {
        cudaFuncSetAttribute(fused_attn_kernel,
                             cudaFuncAttributeMaxDynamicSharedMemorySize, FA_SMEM);
        smem_set = 1;
    }

    dim3 blk2(16, 16);
    proj_qk_kernel<<<dim3(32, 4), 256>>>(x, Wq, bq, Wk, bk);
    proj_v_kernel<<<dim3(64, 4, 4), blk2>>>(x, Wv, bv);
    fused_attn_kernel<<<dim3(32, 2, 4), 256, FA_SMEM>>>(x, out);
}

// round 9
// speedup vs baseline: 1.1424x; 1.1424x over previous
#include <cuda_runtime.h>
#include <cuda_bf16.h>
#include <cstdint>

#define N_PIX 4096
#define BATCH 4
#define CH    256
#define DQK   32

typedef unsigned long long u64;
typedef unsigned int u32;

// ---------------- scratch (device globals) ------------------------------------------
__device__ __nv_bfloat16 g_qh[(size_t)BATCH * N_PIX * DQK];  // Q hi [b][n][32]
__device__ __nv_bfloat16 g_ql[(size_t)BATCH * N_PIX * DQK];  // Q lo
__device__ __nv_bfloat16 g_kh[(size_t)BATCH * N_PIX * DQK];  // K hi [b][m][32]
__device__ __nv_bfloat16 g_kl[(size_t)BATCH * N_PIX * DQK];  // K lo
__device__ __nv_bfloat16 g_vh[(size_t)BATCH * CH * N_PIX];   // V hi [b][d][m]
__device__ __nv_bfloat16 g_vl[(size_t)BATCH * CH * N_PIX];   // V lo

// ---------------- f32x2 helpers ------------------------------------------------------
__device__ __forceinline__ u64 fma2(u64 a, u64 b, u64 c) {
    u64 d;
    asm("fma.rn.f32x2 %0, %1, %2, %3;" : "=l"(d) : "l"(a), "l"(b), "l"(c));
    return d;
}
__device__ __forceinline__ u64 pack2(float x, float y) {
    u64 r;
    asm("mov.b64 %0, {%1, %2};" : "=l"(r) : "f"(x), "f"(y));
    return r;
}
__device__ __forceinline__ float2 unpack2(u64 v) {
    float2 r;
    asm("mov.b64 {%0, %1}, %2;" : "=f"(r.x), "=f"(r.y) : "l"(v));
    return r;
}

// ---------------- split-bf16 helpers --------------------------------------------------
__device__ __forceinline__ void split2(float a, float b, u32& hi, u32& lo) {
    __nv_bfloat162 h = __floats2bfloat162_rn(a, b);
    u32 hraw = *(const u32*)&h;
    float ha = __uint_as_float(hraw << 16);
    float hb = __uint_as_float(hraw & 0xFFFF0000u);
    __nv_bfloat162 l = __floats2bfloat162_rn(a - ha, b - hb);
    hi = hraw;
    lo = *(const u32*)&l;
}
__device__ __forceinline__ void split_store4(__nv_bfloat16* hp, __nv_bfloat16* lp,
                                             float f0, float f1, float f2, float f3)
{
    u32 h0, l0, h1, l1;
    split2(f0, f1, h0, l0);
    split2(f2, f3, h1, l1);
    *(uint2*)hp = make_uint2(h0, h1);
    *(uint2*)lp = make_uint2(l0, l1);
}

// ---------------- smem / cp.async / mma helpers -------------------------------------
__device__ __forceinline__ u32 smem_u32(const void* p) {
    u32 a;
    asm("{ .reg .u64 t; cvta.to.shared.u64 t, %1; cvt.u32.u64 %0, t; }" : "=r"(a) : "l"(p));
    return a;
}
__device__ __forceinline__ void cp16(u32 d, const void* s) {
    asm volatile("cp.async.cg.shared.global [%0], [%1], 16;" :: "r"(d), "l"(s));
}
#define CP_COMMIT() asm volatile("cp.async.commit_group;" ::: "memory")
#define CP_WAIT2()  asm volatile("cp.async.wait_group 2;" ::: "memory")
#define CP_WAIT1()  asm volatile("cp.async.wait_group 1;" ::: "memory")
#define CP_WAIT0()  asm volatile("cp.async.wait_group 0;" ::: "memory")

__device__ __forceinline__ void ldm4(u32 addr, u32& r0, u32& r1, u32& r2, u32& r3) {
    asm volatile("ldmatrix.sync.aligned.m8n8.x4.shared.b16 {%0,%1,%2,%3}, [%4];"
                 : "=r"(r0), "=r"(r1), "=r"(r2), "=r"(r3) : "r"(addr));
}
__device__ __forceinline__ void mma16816(float* c, const u32* a, u32 b0, u32 b1) {
    asm volatile(
        "mma.sync.aligned.m16n8k16.row.col.f32.bf16.bf16.f32 "
        "{%0,%1,%2,%3}, {%4,%5,%6,%7}, {%8,%9}, {%0,%1,%2,%3};"
        : "+f"(c[0]), "+f"(c[1]), "+f"(c[2]), "+f"(c[3])
        : "r"(a[0]), "r"(a[1]), "r"(a[2]), "r"(a[3]), "r"(b0), "r"(b1));
}

// ================== kernel 1: q/k projection (128 px/CTA, split-bf16 out) ==========
__global__ void __launch_bounds__(256) proj_qk_kernel(
    const float* __restrict__ x,
    const float* __restrict__ Wq, const float* __restrict__ bq,
    const float* __restrict__ Wk, const float* __restrict__ bk)
{
    __shared__ float sX[32 * 132];
    __shared__ float sW[32 * 68];

    const int tid = threadIdx.x;
    const int g = tid & 31;          // 4-pixel group
    const int h = tid >> 5;          // 0..7: h<4 -> q, else k
    const int b = blockIdx.y;
    const int n0 = blockIdx.x * 128;
    const bool isq = (h < 4);
    const int dbase = (h & 3) * 8;
    const int woff = (isq ? 0 : 32) + dbase;

    u64 acc[8][2];
#pragma unroll
    for (int i = 0; i < 8; i++) { acc[i][0] = 0; acc[i][1] = 0; }

    for (int c0 = 0; c0 < CH; c0 += 32) {
        __syncthreads();
#pragma unroll
        for (int pass = 0; pass < 4; ++pass) {
            int cc = h + pass * 8;
            const float* src = x + ((size_t)b * CH + c0 + cc) * N_PIX + n0 + g * 4;
            *(float4*)(sX + cc * 132 + g * 4) = *(const float4*)src;
        }
        {
            int d = tid & 31;
            int c4 = (tid >> 5) * 4;
            float4 wq4 = *(const float4*)(Wq + d * CH + c0 + c4);
            float4 wk4 = *(const float4*)(Wk + d * CH + c0 + c4);
            sW[(c4 + 0) * 68 + d] = wq4.x; sW[(c4 + 1) * 68 + d] = wq4.y;
            sW[(c4 + 2) * 68 + d] = wq4.z; sW[(c4 + 3) * 68 + d] = wq4.w;
            sW[(c4 + 0) * 68 + 32 + d] = wk4.x; sW[(c4 + 1) * 68 + 32 + d] = wk4.y;
            sW[(c4 + 2) * 68 + 32 + d] = wk4.z; sW[(c4 + 3) * 68 + 32 + d] = wk4.w;
        }
        __syncthreads();

#pragma unroll 8
        for (int cc = 0; cc < 32; ++cc) {
            float4 xa = *(const float4*)(sX + cc * 132 + g * 4);
            u64 xp0 = pack2(xa.x, xa.y), xp1 = pack2(xa.z, xa.w);
            const float* wp = sW + cc * 68 + woff;
            float4 w0 = *(const float4*)wp;
            float4 w1 = *(const float4*)(wp + 4);
            float wv[8] = {w0.x, w0.y, w0.z, w0.w, w1.x, w1.y, w1.z, w1.w};
#pragma unroll
            for (int i = 0; i < 8; i++) {
                u64 wd = pack2(wv[i], wv[i]);
                acc[i][0] = fma2(wd, xp0, acc[i][0]);
                acc[i][1] = fma2(wd, xp1, acc[i][1]);
            }
        }
    }

    const float* bias = isq ? bq : bk;
    float bb[8];
#pragma unroll
    for (int i = 0; i < 8; i++) bb[i] = bias[dbase + i];
    __nv_bfloat16* oh = (isq ? g_qh : g_kh) + ((size_t)b * N_PIX + n0 + g * 4) * DQK + dbase;
    __nv_bfloat16* ol = (isq ? g_ql : g_kl) + ((size_t)b * N_PIX + n0 + g * 4) * DQK + dbase;
#pragma unroll
    for (int j = 0; j < 4; j++) {
        float v[8];
#pragma unroll
        for (int i = 0; i < 8; i++) {
            float2 t = unpack2(acc[i][j >> 1]);
            v[i] = ((j & 1) ? t.y : t.x) + bb[i];
        }
        u32 hh[4], ll[4];
        split2(v[0], v[1], hh[0], ll[0]);
        split2(v[2], v[3], hh[1], ll[1]);
        split2(v[4], v[5], hh[2], ll[2]);
        split2(v[6], v[7], hh[3], ll[3]);
        *(uint4*)(oh + (size_t)j * DQK) = make_uint4(hh[0], hh[1], hh[2], hh[3]);
        *(uint4*)(ol + (size_t)j * DQK) = make_uint4(ll[0], ll[1], ll[2], ll[3]);
    }
}

// ================== kernel 2: v projection (writes split-bf16 V) ===================
__global__ void __launch_bounds__(256) proj_v_kernel(
    const float* __restrict__ x, const float* __restrict__ Wv, const float* __restrict__ bv)
{
    __shared__ float sA[32][68];
    __shared__ float sB[32][68];

    int b  = blockIdx.z;
    int n0 = blockIdx.x * 64;
    int d0 = blockIdx.y * 64;
    int tx = threadIdx.x, ty = threadIdx.y, tid = ty * 16 + tx;

    float acc[4][4] = {};

    for (int c0 = 0; c0 < CH; c0 += 32) {
        for (int idx = tid; idx < 512; idx += 256) {
            int r = idx >> 3, q = idx & 7;
            float4 w = *(const float4*)(Wv + (size_t)(d0 + r) * CH + c0 + q * 4);
            sA[q * 4 + 0][r] = w.x; sA[q * 4 + 1][r] = w.y;
            sA[q * 4 + 2][r] = w.z; sA[q * 4 + 3][r] = w.w;

            int r2 = idx >> 4, q2 = idx & 15;
            float4 xv = *(const float4*)(x + ((size_t)b * CH + c0 + r2) * N_PIX + n0 + q2 * 4);
            *(float4*)&sB[r2][q2 * 4] = xv;
        }
        __syncthreads();

#pragma unroll
        for (int k = 0; k < 32; k++) {
            float4 a4 = *(const float4*)&sA[k][ty * 4];
            float4 b4 = *(const float4*)&sB[k][tx * 4];
            float av[4] = {a4.x, a4.y, a4.z, a4.w};
            float bw[4] = {b4.x, b4.y, b4.z, b4.w};
#pragma unroll
            for (int i = 0; i < 4; i++)
#pragma unroll
                for (int j = 0; j < 4; j++)
                    acc[i][j] += av[i] * bw[j];
        }
        __syncthreads();
    }

#pragma unroll
    for (int i = 0; i < 4; i++) {
        int d = d0 + ty * 4 + i;
        float bias = bv[d];
        size_t base = ((size_t)b * CH + d) * N_PIX + n0 + tx * 4;
        split_store4(g_vh + base, g_vl + base,
                     acc[i][0] + bias, acc[i][1] + bias,
                     acc[i][2] + bias, acc[i][3] + bias);
    }
}

// ================== kernel 3: fused attention (round-7 proven pipeline) ============
// CTA: 128 queries (n0) x 128 channels (d0); loops m over N_PIX in 128-tiles.
#define FA_QH   0u           // 128 x 40 halves
#define FA_QL   10240u
#define FA_K    20480u       // 2 bufs x (hi 10240 + lo 10240)
#define FA_KBUF 20480u
#define FA_KLO  10240u
#define FA_VH   61440u       // 128 x 136 halves
#define FA_VL   96256u
#define FA_PH   131072u
#define FA_PL   165888u
#define FA_SROW 200704u
#define FA_SINV 201216u
#define FA_SMEM 201728u

__global__ void __launch_bounds__(256, 1) fused_attn_kernel(
    const float* __restrict__ x, float* __restrict__ out)
{
    extern __shared__ char sm[];
    const u32 S = smem_u32(sm);

    const int tid = threadIdx.x;
    const int w = tid >> 5, lane = tid & 31;
    const int b  = blockIdx.z;
    const int n0 = blockIdx.x * 128;
    const int d0 = blockIdx.y * 128;

    const __nv_bfloat16* qh = g_qh + ((size_t)b * N_PIX + n0) * DQK;
    const __nv_bfloat16* ql = g_ql + ((size_t)b * N_PIX + n0) * DQK;
    const __nv_bfloat16* kh = g_kh + (size_t)b * N_PIX * DQK;
    const __nv_bfloat16* kl = g_kl + (size_t)b * N_PIX * DQK;
    const __nv_bfloat16* vh = g_vh + ((size_t)b * CH + d0) * N_PIX;
    const __nv_bfloat16* vl = g_vl + ((size_t)b * CH + d0) * N_PIX;

    auto load_qk32 = [&](u32 sbase, const __nv_bfloat16* hsrc, const __nv_bfloat16* lsrc) {
#pragma unroll
        for (int j = 0; j < 4; ++j) {
            int idx = tid + j * 256;
            int mat = idx >> 9;
            int within = idx & 511;
            int row = within >> 2, c = within & 3;
            const __nv_bfloat16* src = (mat ? lsrc : hsrc) + (size_t)row * DQK + c * 8;
            cp16(sbase + (u32)mat * 10240u + (u32)(row * 40 + c * 8) * 2, src);
        }
    };
    auto load_v = [&](int m0) {
#pragma unroll
        for (int j = 0; j < 16; ++j) {
            int idx = tid + j * 256;
            int mat = idx >> 11;
            int within = idx & 2047;
            int row = within >> 4, c = within & 15;
            const __nv_bfloat16* src = (mat ? vl : vh) + (size_t)row * N_PIX + m0 + c * 8;
            cp16(S + (mat ? FA_VL : FA_VH) + (u32)(row * 136 + c * 8) * 2, src);
        }
    };

    // ---- prologue ----
    load_qk32(S + FA_QH, qh, ql);
    load_qk32(S + FA_K, kh, kl);
    load_v(0);
    CP_COMMIT();
    load_qk32(S + FA_K + FA_KBUF, kh + 128 * DQK, kl + 128 * DQK);
    CP_COMMIT();
    CP_WAIT1();
    __syncthreads();

    float accO[16][4];
#pragma unroll
    for (int i = 0; i < 16; i++)
#pragma unroll
        for (int q = 0; q < 4; q++) accO[i][q] = 0.f;
    float rs0 = 0.f, rs1 = 0.f;

    const int arow = w * 16 + (lane & 15);
    const int acol = (lane >> 4) << 3;
    const int brow = (lane & 7) + ((lane >> 4) & 1) * 8;
    const int bcol = ((lane >> 3) & 1) * 8;

    const int NT = N_PIX / 128;  // 32 m-tiles
    for (int t = 0; t < NT; ++t) {
        CP_WAIT2();
        __syncthreads();

        // ---- E phase ----
        const u32 kb = S + FA_K + (u32)(t & 1) * FA_KBUF;
        float accE[16][4];
#pragma unroll
        for (int i = 0; i < 16; i++)
#pragma unroll
            for (int q = 0; q < 4; q++) accE[i][q] = 0.f;

#pragma unroll
        for (int kk = 0; kk < 32; kk += 16) {
            u32 ah[4], al[4];
            u32 ao = (u32)(arow * 40 + acol + kk) * 2;
            ldm4(S + FA_QH + ao, ah[0], ah[1], ah[2], ah[3]);
            ldm4(S + FA_QL + ao, al[0], al[1], al[2], al[3]);
#pragma unroll
            for (int nf = 0; nf < 8; nf++) {
                u32 bo = (u32)((nf * 16 + brow) * 40 + bcol + kk) * 2;
                u32 bh[4], bl[4];
                ldm4(kb + bo, bh[0], bh[1], bh[2], bh[3]);
                ldm4(kb + FA_KLO + bo, bl[0], bl[1], bl[2], bl[3]);
                mma16816(accE[nf * 2],     ah, bh[0], bh[1]);
                mma16816(accE[nf * 2],     ah, bl[0], bl[1]);
                mma16816(accE[nf * 2],     al, bh[0], bh[1]);
                mma16816(accE[nf * 2 + 1], ah, bh[2], bh[3]);
                mma16816(accE[nf * 2 + 1], ah, bl[2], bl[3]);
                mma16816(accE[nf * 2 + 1], al, bh[2], bh[3]);
            }
        }

        // ---- exp + rowsum + split-bf16 store to P smem ----
        {
            const int prow = w * 16 + (lane >> 2);
            const int pcol = 2 * (lane & 3);
#pragma unroll
            for (int nf = 0; nf < 16; nf++) {
                float e0 = __expf(accE[nf][0]);
                float e1 = __expf(accE[nf][1]);
                float e2 = __expf(accE[nf][2]);
                float e3 = __expf(accE[nf][3]);
                rs0 += e0 + e1;
                rs1 += e2 + e3;
                u32 hi0, lo0, hi1, lo1;
                split2(e0, e1, hi0, lo0);
                split2(e2, e3, hi1, lo1);
                u32 off0 = (u32)(prow * 136 + nf * 8 + pcol) * 2;
                u32 off1 = off0 + 8u * 136u * 2u;
                *(u32*)(sm + FA_PH + off0) = hi0;
                *(u32*)(sm + FA_PL + off0) = lo0;
                *(u32*)(sm + FA_PH + off1) = hi1;
                *(u32*)(sm + FA_PL + off1) = lo1;
            }
        }
        __syncthreads();

        CP_WAIT1();

        // ---- PV phase ----
#pragma unroll
        for (int ks = 0; ks < 8; ks++) {
            u32 ah[4], al[4];
            u32 ao = (u32)(arow * 136 + acol + ks * 16) * 2;
            ldm4(S + FA_VH + ao, ah[0], ah[1], ah[2], ah[3]);
            ldm4(S + FA_VL + ao, al[0], al[1], al[2], al[3]);
#pragma unroll
            for (int nf = 0; nf < 8; nf++) {
                u32 bo = (u32)((nf * 16 + brow) * 136 + bcol + ks * 16) * 2;
                u32 bh[4], bl[4];
                ldm4(S + FA_PH + bo, bh[0], bh[1], bh[2], bh[3]);
                ldm4(S + FA_PL + bo, bl[0], bl[1], bl[2], bl[3]);
                mma16816(accO[nf * 2],     ah, bh[0], bh[1]);
                mma16816(accO[nf * 2],     ah, bl[0], bl[1]);
                mma16816(accO[nf * 2],     al, bh[0], bh[1]);
                mma16816(accO[nf * 2 + 1], ah, bh[2], bh[3]);
                mma16816(accO[nf * 2 + 1], ah, bl[2], bl[3]);
                mma16816(accO[nf * 2 + 1], al, bh[2], bh[3]);
            }
        }
        __syncthreads();

        // ---- issue next loads ----
        {
            int tv = t + 1 < NT ? t + 1 : NT - 1;
            int tk = t + 2 < NT ? t + 2 : NT - 1;
            load_v(tv * 128);
            CP_COMMIT();
            load_qk32(S + FA_K + (u32)(t & 1) * FA_KBUF,
                      kh + (size_t)tk * 128 * DQK, kl + (size_t)tk * 128 * DQK);
            CP_COMMIT();
        }
    }

    // ---- row sums: quad-reduce, then -> 1/sum ----
    rs0 += __shfl_xor_sync(0xffffffffu, rs0, 1);
    rs0 += __shfl_xor_sync(0xffffffffu, rs0, 2);
    rs1 += __shfl_xor_sync(0xffffffffu, rs1, 1);
    rs1 += __shfl_xor_sync(0xffffffffu, rs1, 2);
    if ((lane & 3) == 0) {
        ((float*)(sm + FA_SROW))[w * 16 + (lane >> 2)] = rs0;
        ((float*)(sm + FA_SROW))[w * 16 + (lane >> 2) + 8] = rs1;
    }
    __syncthreads();
    if (tid < 128)
        ((float*)(sm + FA_SINV))[tid] = 1.0f / ((float*)(sm + FA_SROW))[tid];
    __syncthreads();

    // ---- epilogue: out = accO * rinv[n] + x ----
    const float* sinv = (const float*)(sm + FA_SINV);
    const int er = lane >> 2;
    const int ec = 2 * (lane & 3);
#pragma unroll
    for (int nf = 0; nf < 16; nf++) {
        const int n = nf * 8 + ec;
        float2 rv = *(const float2*)(sinv + n);
        const int d = d0 + w * 16 + er;
        size_t o1 = ((size_t)b * CH + d) * N_PIX + n0 + n;
        size_t o2 = o1 + (size_t)8 * N_PIX;
        float2 x1 = *(const float2*)(x + o1);
        float2 x2 = *(const float2*)(x + o2);
        *(float2*)(out + o1) = make_float2(accO[nf][0] * rv.x + x1.x,
                                           accO[nf][1] * rv.y + x1.y);
        *(float2*)(out + o2) = make_float2(accO[nf][2] * rv.x + x2.x,
                                           accO[nf][3] * rv.y + x2.y);
    }
}

// ================== launch =========================================================
extern "C" void kernel_launch(void* const* d_in, const int* in_sizes, int n_in,
                              void* d_out, int out_size)
{
    (void)in_sizes; (void)n_in; (void)out_size;
    const float* x  = (const float*)d_in[0];
    const float* Wq = (const float*)d_in[1];
    const float* bq = (const float*)d_in[2];
    const float* Wk = (const float*)d_in[3];
    const float* bk = (const float*)d_in[4];
    const float* Wv = (const float*)d_in[5];
    const float* bv = (const float*)d_in[6];
    float* out = (float*)d_out;

    static int smem_set = 0;
    if (!smem_set) {
        cudaFuncSetAttribute(fused_attn_kernel,
                             cudaFuncAttributeMaxDynamicSharedMemorySize, FA_SMEM);
        smem_set = 1;
    }

    dim3 blk2(16, 16);
    proj_qk_kernel<<<dim3(32, 4), 256>>>(x, Wq, bq, Wk, bk);
    proj_v_kernel<<<dim3(64, 4, 4), blk2>>>(x, Wv, bv);
    fused_attn_kernel<<<dim3(32, 2, 4), 256, FA_SMEM>>>(x, out);
}

// round 10
// speedup vs baseline: 1.3356x; 1.1691x over previous
#include <cuda_runtime.h>
#include <cuda_bf16.h>
#include <cstdint>

#define N_PIX 4096
#define BATCH 4
#define CH    256
#define DQK   32

typedef unsigned long long u64;
typedef unsigned int u32;

// ---------------- scratch (device globals) ------------------------------------------
__device__ __nv_bfloat16 g_qh[(size_t)BATCH * N_PIX * DQK];  // Q hi [b][n][32]
__device__ __nv_bfloat16 g_ql[(size_t)BATCH * N_PIX * DQK];  // Q lo
__device__ __nv_bfloat16 g_kh[(size_t)BATCH * N_PIX * DQK];  // K hi [b][m][32]
__device__ __nv_bfloat16 g_kl[(size_t)BATCH * N_PIX * DQK];  // K lo
__device__ __nv_bfloat16 g_vh[(size_t)BATCH * CH * N_PIX];   // V hi [b][d][m]
__device__ __nv_bfloat16 g_vl[(size_t)BATCH * CH * N_PIX];   // V lo

// ---------------- f32x2 helpers ------------------------------------------------------
__device__ __forceinline__ u64 fma2(u64 a, u64 b, u64 c) {
    u64 d;
    asm("fma.rn.f32x2 %0, %1, %2, %3;" : "=l"(d) : "l"(a), "l"(b), "l"(c));
    return d;
}
__device__ __forceinline__ u64 pack2(float x, float y) {
    u64 r;
    asm("mov.b64 %0, {%1, %2};" : "=l"(r) : "f"(x), "f"(y));
    return r;
}
__device__ __forceinline__ float2 unpack2(u64 v) {
    float2 r;
    asm("mov.b64 {%0, %1}, %2;" : "=f"(r.x), "=f"(r.y) : "l"(v));
    return r;
}

// ---------------- split-bf16 helpers --------------------------------------------------
__device__ __forceinline__ void split2(float a, float b, u32& hi, u32& lo) {
    __nv_bfloat162 h = __floats2bfloat162_rn(a, b);
    u32 hraw = *(const u32*)&h;
    float ha = __uint_as_float(hraw << 16);
    float hb = __uint_as_float(hraw & 0xFFFF0000u);
    __nv_bfloat162 l = __floats2bfloat162_rn(a - ha, b - hb);
    hi = hraw;
    lo = *(const u32*)&l;
}
__device__ __forceinline__ void split_store4(__nv_bfloat16* hp, __nv_bfloat16* lp,
                                             float f0, float f1, float f2, float f3)
{
    u32 h0, l0, h1, l1;
    split2(f0, f1, h0, l0);
    split2(f2, f3, h1, l1);
    *(uint2*)hp = make_uint2(h0, h1);
    *(uint2*)lp = make_uint2(l0, l1);
}

// ---------------- smem / cp.async / mma helpers -------------------------------------
__device__ __forceinline__ u32 smem_u32(const void* p) {
    u32 a;
    asm("{ .reg .u64 t; cvta.to.shared.u64 t, %1; cvt.u32.u64 %0, t; }" : "=r"(a) : "l"(p));
    return a;
}
__device__ __forceinline__ void cp16(u32 d, const void* s) {
    asm volatile("cp.async.cg.shared.global [%0], [%1], 16;" :: "r"(d), "l"(s));
}
#define CP_COMMIT() asm volatile("cp.async.commit_group;" ::: "memory")
#define CP_WAIT2()  asm volatile("cp.async.wait_group 2;" ::: "memory")
#define CP_WAIT1()  asm volatile("cp.async.wait_group 1;" ::: "memory")
#define CP_WAIT0()  asm volatile("cp.async.wait_group 0;" ::: "memory")

__device__ __forceinline__ void ldm4(u32 addr, u32& r0, u32& r1, u32& r2, u32& r3) {
    asm volatile("ldmatrix.sync.aligned.m8n8.x4.shared.b16 {%0,%1,%2,%3}, [%4];"
                 : "=r"(r0), "=r"(r1), "=r"(r2), "=r"(r3) : "r"(addr));
}
__device__ __forceinline__ void mma16816(float* c, const u32* a, u32 b0, u32 b1) {
    asm volatile(
        "mma.sync.aligned.m16n8k16.row.col.f32.bf16.bf16.f32 "
        "{%0,%1,%2,%3}, {%4,%5,%6,%7}, {%8,%9}, {%0,%1,%2,%3};"
        : "+f"(c[0]), "+f"(c[1]), "+f"(c[2]), "+f"(c[3])
        : "r"(a[0]), "r"(a[1]), "r"(a[2]), "r"(a[3]), "r"(b0), "r"(b1));
}

// ================== kernel 1: q/k projection (128 px/CTA, split-bf16 out) ==========
__global__ void __launch_bounds__(256) proj_qk_kernel(
    const float* __restrict__ x,
    const float* __restrict__ Wq, const float* __restrict__ bq,
    const float* __restrict__ Wk, const float* __restrict__ bk)
{
    __shared__ float sX[32 * 132];
    __shared__ float sW[32 * 68];

    const int tid = threadIdx.x;
    const int g = tid & 31;
    const int h = tid >> 5;
    const int b = blockIdx.y;
    const int n0 = blockIdx.x * 128;
    const bool isq = (h < 4);
    const int dbase = (h & 3) * 8;
    const int woff = (isq ? 0 : 32) + dbase;

    u64 acc[8][2];
#pragma unroll
    for (int i = 0; i < 8; i++) { acc[i][0] = 0; acc[i][1] = 0; }

    for (int c0 = 0; c0 < CH; c0 += 32) {
        __syncthreads();
#pragma unroll
        for (int pass = 0; pass < 4; ++pass) {
            int cc = h + pass * 8;
            const float* src = x + ((size_t)b * CH + c0 + cc) * N_PIX + n0 + g * 4;
            *(float4*)(sX + cc * 132 + g * 4) = *(const float4*)src;
        }
        {
            int d = tid & 31;
            int c4 = (tid >> 5) * 4;
            float4 wq4 = *(const float4*)(Wq + d * CH + c0 + c4);
            float4 wk4 = *(const float4*)(Wk + d * CH + c0 + c4);
            sW[(c4 + 0) * 68 + d] = wq4.x; sW[(c4 + 1) * 68 + d] = wq4.y;
            sW[(c4 + 2) * 68 + d] = wq4.z; sW[(c4 + 3) * 68 + d] = wq4.w;
            sW[(c4 + 0) * 68 + 32 + d] = wk4.x; sW[(c4 + 1) * 68 + 32 + d] = wk4.y;
            sW[(c4 + 2) * 68 + 32 + d] = wk4.z; sW[(c4 + 3) * 68 + 32 + d] = wk4.w;
        }
        __syncthreads();

#pragma unroll 8
        for (int cc = 0; cc < 32; ++cc) {
            float4 xa = *(const float4*)(sX + cc * 132 + g * 4);
            u64 xp0 = pack2(xa.x, xa.y), xp1 = pack2(xa.z, xa.w);
            const float* wp = sW + cc * 68 + woff;
            float4 w0 = *(const float4*)wp;
            float4 w1 = *(const float4*)(wp + 4);
            float wv[8] = {w0.x, w0.y, w0.z, w0.w, w1.x, w1.y, w1.z, w1.w};
#pragma unroll
            for (int i = 0; i < 8; i++) {
                u64 wd = pack2(wv[i], wv[i]);
                acc[i][0] = fma2(wd, xp0, acc[i][0]);
                acc[i][1] = fma2(wd, xp1, acc[i][1]);
            }
        }
    }

    const float* bias = isq ? bq : bk;
    float bb[8];
#pragma unroll
    for (int i = 0; i < 8; i++) bb[i] = bias[dbase + i];
    __nv_bfloat16* oh = (isq ? g_qh : g_kh) + ((size_t)b * N_PIX + n0 + g * 4) * DQK + dbase;
    __nv_bfloat16* ol = (isq ? g_ql : g_kl) + ((size_t)b * N_PIX + n0 + g * 4) * DQK + dbase;
#pragma unroll
    for (int j = 0; j < 4; j++) {
        float v[8];
#pragma unroll
        for (int i = 0; i < 8; i++) {
            float2 t = unpack2(acc[i][j >> 1]);
            v[i] = ((j & 1) ? t.y : t.x) + bb[i];
        }
        u32 hh[4], ll[4];
        split2(v[0], v[1], hh[0], ll[0]);
        split2(v[2], v[3], hh[1], ll[1]);
        split2(v[4], v[5], hh[2], ll[2]);
        split2(v[6], v[7], hh[3], ll[3]);
        *(uint4*)(oh + (size_t)j * DQK) = make_uint4(hh[0], hh[1], hh[2], hh[3]);
        *(uint4*)(ol + (size_t)j * DQK) = make_uint4(ll[0], ll[1], ll[2], ll[3]);
    }
}

// ================== kernel 2: v projection (writes split-bf16 V) ===================
__global__ void __launch_bounds__(256) proj_v_kernel(
    const float* __restrict__ x, const float* __restrict__ Wv, const float* __restrict__ bv)
{
    __shared__ float sA[32][68];
    __shared__ float sB[32][68];

    int b  = blockIdx.z;
    int n0 = blockIdx.x * 64;
    int d0 = blockIdx.y * 64;
    int tx = threadIdx.x, ty = threadIdx.y, tid = ty * 16 + tx;

    float acc[4][4] = {};

    for (int c0 = 0; c0 < CH; c0 += 32) {
        for (int idx = tid; idx < 512; idx += 256) {
            int r = idx >> 3, q = idx & 7;
            float4 w = *(const float4*)(Wv + (size_t)(d0 + r) * CH + c0 + q * 4);
            sA[q * 4 + 0][r] = w.x; sA[q * 4 + 1][r] = w.y;
            sA[q * 4 + 2][r] = w.z; sA[q * 4 + 3][r] = w.w;

            int r2 = idx >> 4, q2 = idx & 15;
            float4 xv = *(const float4*)(x + ((size_t)b * CH + c0 + r2) * N_PIX + n0 + q2 * 4);
            *(float4*)&sB[r2][q2 * 4] = xv;
        }
        __syncthreads();

#pragma unroll
        for (int k = 0; k < 32; k++) {
            float4 a4 = *(const float4*)&sA[k][ty * 4];
            float4 b4 = *(const float4*)&sB[k][tx * 4];
            float av[4] = {a4.x, a4.y, a4.z, a4.w};
            float bw[4] = {b4.x, b4.y, b4.z, b4.w};
#pragma unroll
            for (int i = 0; i < 4; i++)
#pragma unroll
                for (int j = 0; j < 4; j++)
                    acc[i][j] += av[i] * bw[j];
        }
        __syncthreads();
    }

#pragma unroll
    for (int i = 0; i < 4; i++) {
        int d = d0 + ty * 4 + i;
        float bias = bv[d];
        size_t base = ((size_t)b * CH + d) * N_PIX + n0 + tx * 4;
        split_store4(g_vh + base, g_vl + base,
                     acc[i][0] + bias, acc[i][1] + bias,
                     acc[i][2] + bias, acc[i][3] + bias);
    }
}

// ================== kernel 3: fused attention, full-d CTA, register-P ==============
// CTA: 128 queries (n0) x ALL 256 channels. O^T[n][d] = P[n][m] . V_B; P lives in regs.
#define FA_QH   0u           // 128 x 40 halves
#define FA_QL   10240u
#define FA_K    20480u       // 2 bufs x (hi 10240 + lo 10240)
#define FA_KBUF 20480u
#define FA_KLO  10240u
#define FA_V0   61440u       // d-half 0: VH(34816) + VL(34816), row pitch 136 halves
#define FA_V1   131072u      // d-half 1
#define FA_VLO  34816u
#define FA_SROW 200704u
#define FA_SINV 201216u
#define FA_SMEM 201728u
#define FA_STG  61440u       // epilogue staging: 256 x 132 floats (reuses V bufs)

__global__ void __launch_bounds__(256, 1) fused_attn_kernel(
    const float* __restrict__ x, float* __restrict__ out)
{
    extern __shared__ char sm[];
    const u32 S = smem_u32(sm);

    const int tid = threadIdx.x;
    const int w = tid >> 5, lane = tid & 31;
    const int b  = blockIdx.z;
    const int n0 = blockIdx.x * 128;

    const __nv_bfloat16* qh = g_qh + ((size_t)b * N_PIX + n0) * DQK;
    const __nv_bfloat16* ql = g_ql + ((size_t)b * N_PIX + n0) * DQK;
    const __nv_bfloat16* kh = g_kh + (size_t)b * N_PIX * DQK;
    const __nv_bfloat16* kl = g_kl + (size_t)b * N_PIX * DQK;
    const __nv_bfloat16* vh = g_vh + (size_t)b * CH * N_PIX;
    const __nv_bfloat16* vl = g_vl + (size_t)b * CH * N_PIX;

    auto load_q = [&]() {
#pragma unroll
        for (int j = 0; j < 4; ++j) {
            int idx = tid + j * 256;
            int mat = idx >> 9;
            int within = idx & 511;
            int row = within >> 2, c = within & 3;
            const __nv_bfloat16* src = (mat ? ql : qh) + (size_t)row * DQK + c * 8;
            cp16(S + FA_QH + (u32)mat * 10240u + (u32)(row * 40 + c * 8) * 2, src);
        }
    };
    auto load_k = [&](int t2, u32 kbuf) {
#pragma unroll
        for (int j = 0; j < 4; ++j) {
            int idx = tid + j * 256;
            int mat = idx >> 9;
            int within = idx & 511;
            int row = within >> 2, c = within & 3;
            const __nv_bfloat16* src = (mat ? kl : kh) + ((size_t)t2 * 128 + row) * DQK + c * 8;
            cp16(kbuf + (u32)mat * FA_KLO + (u32)(row * 40 + c * 8) * 2, src);
        }
    };
    auto load_v = [&](int m0, int hf) {
        const u32 vb = S + (hf ? FA_V1 : FA_V0);
#pragma unroll
        for (int j = 0; j < 16; ++j) {
            int idx = tid + j * 256;
            int mat = idx >> 11;
            int within = idx & 2047;
            int row = within >> 4, c = within & 15;
            const __nv_bfloat16* src = (mat ? vl : vh)
                + ((size_t)(hf * 128 + row)) * N_PIX + m0 + c * 8;
            cp16(vb + (mat ? FA_VLO : 0u) + (u32)(row * 136 + c * 8) * 2, src);
        }
    };

    // ---- prologue: G1 = Q + K(0);  G2 = V(0,h0);  G3 = V(0,h1) + K(1) ----
    load_q(); load_k(0, S + FA_K); CP_COMMIT();
    load_v(0, 0); CP_COMMIT();
    load_v(0, 1); load_k(1, S + FA_K + FA_KBUF); CP_COMMIT();

    float accO[32][4];
#pragma unroll
    for (int i = 0; i < 32; i++)
#pragma unroll
        for (int q = 0; q < 4; q++) accO[i][q] = 0.f;
    float rs0 = 0.f, rs1 = 0.f;

    const int arow = w * 16 + (lane & 15);
    const int acol = (lane >> 4) << 3;
    const int brow = (lane & 7) + ((lane >> 4) & 1) * 8;
    const int bcol = ((lane >> 3) & 1) * 8;

    const int NT = N_PIX / 128;  // 32 m-tiles
    for (int t = 0; t < NT; ++t) {
        CP_WAIT2();               // K(t) retired (all but newest 2 groups)
        __syncthreads();

        // ---- E phase: E[128n x 128m] = Q.K^T, 3-term split ----
        const u32 kb = S + FA_K + (u32)(t & 1) * FA_KBUF;
        float accE[16][4];
#pragma unroll
        for (int i = 0; i < 16; i++)
#pragma unroll
            for (int q = 0; q < 4; q++) accE[i][q] = 0.f;

#pragma unroll
        for (int kk = 0; kk < 32; kk += 16) {
            u32 ah[4], al[4];
            u32 ao = (u32)(arow * 40 + acol + kk) * 2;
            ldm4(S + FA_QH + ao, ah[0], ah[1], ah[2], ah[3]);
            ldm4(S + FA_QL + ao, al[0], al[1], al[2], al[3]);
#pragma unroll
            for (int nf = 0; nf < 8; nf++) {
                u32 bo = (u32)((nf * 16 + brow) * 40 + bcol + kk) * 2;
                u32 bh[4], bl[4];
                ldm4(kb + bo, bh[0], bh[1], bh[2], bh[3]);
                ldm4(kb + FA_KLO + bo, bl[0], bl[1], bl[2], bl[3]);
                mma16816(accE[nf * 2],     ah, bh[0], bh[1]);
                mma16816(accE[nf * 2],     ah, bl[0], bl[1]);
                mma16816(accE[nf * 2],     al, bh[0], bh[1]);
                mma16816(accE[nf * 2 + 1], ah, bh[2], bh[3]);
                mma16816(accE[nf * 2 + 1], ah, bl[2], bl[3]);
                mma16816(accE[nf * 2 + 1], al, bh[2], bh[3]);
            }
        }

        // ---- exp + rowsum + build P A-fragments in registers (FA2 layout trick) ----
        u32 pah[8][4], pal[8][4];
#pragma unroll
        for (int ks = 0; ks < 8; ks++) {
            float e00 = __expf(accE[2 * ks][0]);
            float e01 = __expf(accE[2 * ks][1]);
            float e02 = __expf(accE[2 * ks][2]);
            float e03 = __expf(accE[2 * ks][3]);
            float e10 = __expf(accE[2 * ks + 1][0]);
            float e11 = __expf(accE[2 * ks + 1][1]);
            float e12 = __expf(accE[2 * ks + 1][2]);
            float e13 = __expf(accE[2 * ks + 1][3]);
            rs0 += (e00 + e01) + (e10 + e11);
            rs1 += (e02 + e03) + (e12 + e13);
            split2(e00, e01, pah[ks][0], pal[ks][0]);   // a0: (r,   k0..1)
            split2(e02, e03, pah[ks][1], pal[ks][1]);   // a1: (r+8, k0..1)
            split2(e10, e11, pah[ks][2], pal[ks][2]);   // a2: (r,   k8..9)
            split2(e12, e13, pah[ks][3], pal[ks][3]);   // a3: (r+8, k8..9)
        }

        // ---- PV half 0 (d 0..127): O^T += P . V ----
        CP_WAIT1();               // V(t,h0) retired
        __syncthreads();
        {
            const u32 vb = S + FA_V0;
#pragma unroll
            for (int ks = 0; ks < 8; ks++) {
#pragma unroll
                for (int dg = 0; dg < 8; dg++) {
                    u32 boff = (u32)((dg * 16 + brow) * 136 + bcol + ks * 16) * 2;
                    u32 bh[4], bl[4];
                    ldm4(vb + boff, bh[0], bh[1], bh[2], bh[3]);
                    ldm4(vb + FA_VLO + boff, bl[0], bl[1], bl[2], bl[3]);
                    mma16816(accO[dg * 2],     pah[ks], bh[0], bh[1]);
                    mma16816(accO[dg * 2],     pal[ks], bh[0], bh[1]);
                    mma16816(accO[dg * 2],     pah[ks], bl[0], bl[1]);
                    mma16816(accO[dg * 2 + 1], pah[ks], bh[2], bh[3]);
                    mma16816(accO[dg * 2 + 1], pal[ks], bh[2], bh[3]);
                    mma16816(accO[dg * 2 + 1], pah[ks], bl[2], bl[3]);
                }
            }
        }
        __syncthreads();          // all warps done reading V0
        {
            int tv = (t + 1 < NT) ? t + 1 : NT - 1;
            load_v(tv * 128, 0);
            CP_COMMIT();
        }

        // ---- PV half 1 (d 128..255) ----
        CP_WAIT1();               // V(t,h1)+K(t+1) retired
        __syncthreads();
        {
            const u32 vb = S + FA_V1;
#pragma unroll
            for (int ks = 0; ks < 8; ks++) {
#pragma unroll
                for (int dg = 0; dg < 8; dg++) {
                    u32 boff = (u32)((dg * 16 + brow) * 136 + bcol + ks * 16) * 2;
                    u32 bh[4], bl[4];
                    ldm4(vb + boff, bh[0], bh[1], bh[2], bh[3]);
                    ldm4(vb + FA_VLO + boff, bl[0], bl[1], bl[2], bl[3]);
                    mma16816(accO[16 + dg * 2],     pah[ks], bh[0], bh[1]);
                    mma16816(accO[16 + dg * 2],     pal[ks], bh[0], bh[1]);
                    mma16816(accO[16 + dg * 2],     pah[ks], bl[0], bl[1]);
                    mma16816(accO[16 + dg * 2 + 1], pah[ks], bh[2], bh[3]);
                    mma16816(accO[16 + dg * 2 + 1], pal[ks], bh[2], bh[3]);
                    mma16816(accO[16 + dg * 2 + 1], pah[ks], bl[2], bl[3]);
                }
            }
        }
        __syncthreads();          // all warps done reading V1
        {
            int tv = (t + 1 < NT) ? t + 1 : NT - 1;
            int tk = (t + 2 < NT) ? t + 2 : NT - 1;
            load_v(tv * 128, 1);
            load_k(tk, S + FA_K + (u32)(t & 1) * FA_KBUF);
            CP_COMMIT();
        }
    }

    // drain pending dummy copies before reusing V smem as staging
    CP_WAIT0();
    __syncthreads();

    // ---- row sums: quad-reduce, then -> 1/sum ----
    rs0 += __shfl_xor_sync(0xffffffffu, rs0, 1);
    rs0 += __shfl_xor_sync(0xffffffffu, rs0, 2);
    rs1 += __shfl_xor_sync(0xffffffffu, rs1, 1);
    rs1 += __shfl_xor_sync(0xffffffffu, rs1, 2);
    if ((lane & 3) == 0) {
        ((float*)(sm + FA_SROW))[w * 16 + (lane >> 2)] = rs0;
        ((float*)(sm + FA_SROW))[w * 16 + (lane >> 2) + 8] = rs1;
    }
    __syncthreads();
    if (tid < 128)
        ((float*)(sm + FA_SINV))[tid] = 1.0f / ((float*)(sm + FA_SROW))[tid];
    __syncthreads();

    // ---- epilogue phase 1: O^T regs -> staging smem [d][n], scaled by rinv[n] ----
    {
        float* stg = (float*)(sm + FA_STG);
        const float* sinv = (const float*)(sm + FA_SINV);
        const int er = lane >> 2;
        const int ec = 2 * (lane & 3);
        const int n = w * 16 + er;
        const float s0 = sinv[n];
        const float s1 = sinv[n + 8];
#pragma unroll
        for (int idx = 0; idx < 32; idx++) {
            const int hf = idx >> 4, rem = idx & 15;
            const int dg = rem >> 1, f = rem & 1;
            const int d = hf * 128 + dg * 16 + f * 8 + ec;
            stg[d * 132 + n]           = accO[idx][0] * s0;
            stg[(d + 1) * 132 + n]     = accO[idx][1] * s0;
            stg[d * 132 + n + 8]       = accO[idx][2] * s1;
            stg[(d + 1) * 132 + n + 8] = accO[idx][3] * s1;
        }
    }
    __syncthreads();

    // ---- epilogue phase 2: coalesced out = stg + x ----
    {
        const float* stg = (const float*)(sm + FA_STG);
        const int dl = tid >> 5;          // 0..7
        const int nn = (tid & 31) * 4;    // 0..124
#pragma unroll 4
        for (int it = 0; it < 32; it++) {
            const int d = it * 8 + dl;
            float4 v = *(const float4*)&stg[d * 132 + nn];
            size_t go = ((size_t)b * CH + d) * N_PIX + n0 + nn;
            float4 xv = *(const float4*)(x + go);
            *(float4*)(out + go) = make_float4(v.x + xv.x, v.y + xv.y,
                                               v.z + xv.z, v.w + xv.w);
        }
    }
}

// ================== launch =========================================================
extern "C" void kernel_launch(void* const* d_in, const int* in_sizes, int n_in,
                              void* d_out, int out_size)
{
    (void)in_sizes; (void)n_in; (void)out_size;
    const float* x  = (const float*)d_in[0];
    const float* Wq = (const float*)d_in[1];
    const float* bq = (const float*)d_in[2];
    const float* Wk = (const float*)d_in[3];
    const float* bk = (const float*)d_in[4];
    const float* Wv = (const float*)d_in[5];
    const float* bv = (const float*)d_in[6];
    float* out = (float*)d_out;

    static int smem_set = 0;
    if (!smem_set) {
        cudaFuncSetAttribute(fused_attn_kernel,
                             cudaFuncAttributeMaxDynamicSharedMemorySize, FA_SMEM);
        smem_set = 1;
    }

    dim3 blk2(16, 16);
    proj_qk_kernel<<<dim3(32, 4), 256>>>(x, Wq, bq, Wk, bk);
    proj_v_kernel<<<dim3(64, 4, 4), blk2>>>(x, Wv, bv);
    fused_attn_kernel<<<dim3(32, 1, 4), 256, FA_SMEM>>>(x, out);
}

// round 11
// speedup vs baseline: 2.2625x; 1.6940x over previous
#include <cuda_runtime.h>
#include <cuda_bf16.h>
#include <cuda_fp16.h>
#include <cstdint>

#define N_PIX 4096
#define BATCH 4
#define CH    256
#define DQK   32

typedef unsigned long long u64;
typedef unsigned int u32;

// ---------------- scratch (device globals) ------------------------------------------
__device__ __nv_bfloat16 g_qh[(size_t)BATCH * N_PIX * DQK];  // Q hi [b][n][32]
__device__ __nv_bfloat16 g_ql[(size_t)BATCH * N_PIX * DQK];  // Q lo
__device__ __nv_bfloat16 g_kh[(size_t)BATCH * N_PIX * DQK];  // K hi [b][m][32]
__device__ __nv_bfloat16 g_kl[(size_t)BATCH * N_PIX * DQK];  // K lo
__device__ __half        g_vf[(size_t)BATCH * CH * N_PIX];   // V fp16 [b][d][m]

// ---------------- f32x2 helpers ------------------------------------------------------
__device__ __forceinline__ u64 fma2(u64 a, u64 b, u64 c) {
    u64 d;
    asm("fma.rn.f32x2 %0, %1, %2, %3;" : "=l"(d) : "l"(a), "l"(b), "l"(c));
    return d;
}
__device__ __forceinline__ u64 pack2(float x, float y) {
    u64 r;
    asm("mov.b64 %0, {%1, %2};" : "=l"(r) : "f"(x), "f"(y));
    return r;
}
__device__ __forceinline__ float2 unpack2(u64 v) {
    float2 r;
    asm("mov.b64 {%0, %1}, %2;" : "=f"(r.x), "=f"(r.y) : "l"(v));
    return r;
}

// ---------------- split-bf16 helper ---------------------------------------------------
__device__ __forceinline__ void split2(float a, float b, u32& hi, u32& lo) {
    __nv_bfloat162 h = __floats2bfloat162_rn(a, b);
    u32 hraw = *(const u32*)&h;
    float ha = __uint_as_float(hraw << 16);
    float hb = __uint_as_float(hraw & 0xFFFF0000u);
    __nv_bfloat162 l = __floats2bfloat162_rn(a - ha, b - hb);
    hi = hraw;
    lo = *(const u32*)&l;
}

// ---------------- smem / cp.async / mma helpers -------------------------------------
__device__ __forceinline__ u32 smem_u32(const void* p) {
    u32 a;
    asm("{ .reg .u64 t; cvta.to.shared.u64 t, %1; cvt.u32.u64 %0, t; }" : "=r"(a) : "l"(p));
    return a;
}
__device__ __forceinline__ void cp16(u32 d, const void* s) {
    asm volatile("cp.async.cg.shared.global [%0], [%1], 16;" :: "r"(d), "l"(s));
}
#define CP_COMMIT() asm volatile("cp.async.commit_group;" ::: "memory")
#define CP_WAIT2()  asm volatile("cp.async.wait_group 2;" ::: "memory")
#define CP_WAIT1()  asm volatile("cp.async.wait_group 1;" ::: "memory")
#define CP_WAIT0()  asm volatile("cp.async.wait_group 0;" ::: "memory")

__device__ __forceinline__ void ldm4(u32 addr, u32& r0, u32& r1, u32& r2, u32& r3) {
    asm volatile("ldmatrix.sync.aligned.m8n8.x4.shared.b16 {%0,%1,%2,%3}, [%4];"
                 : "=r"(r0), "=r"(r1), "=r"(r2), "=r"(r3) : "r"(addr));
}
// bf16 MMA (E phase)
__device__ __forceinline__ void mma16816(float* c, const u32* a, u32 b0, u32 b1) {
    asm volatile(
        "mma.sync.aligned.m16n8k16.row.col.f32.bf16.bf16.f32 "
        "{%0,%1,%2,%3}, {%4,%5,%6,%7}, {%8,%9}, {%0,%1,%2,%3};"
        : "+f"(c[0]), "+f"(c[1]), "+f"(c[2]), "+f"(c[3])
        : "r"(a[0]), "r"(a[1]), "r"(a[2]), "r"(a[3]), "r"(b0), "r"(b1));
}
// fp16 MMA (PV phase)
__device__ __forceinline__ void mma16816h(float* c, const u32* a, u32 b0, u32 b1) {
    asm volatile(
        "mma.sync.aligned.m16n8k16.row.col.f32.f16.f16.f32 "
        "{%0,%1,%2,%3}, {%4,%5,%6,%7}, {%8,%9}, {%0,%1,%2,%3};"
        : "+f"(c[0]), "+f"(c[1]), "+f"(c[2]), "+f"(c[3])
        : "r"(a[0]), "r"(a[1]), "r"(a[2]), "r"(a[3]), "r"(b0), "r"(b1));
}

// ================== kernel 1: q/k projection (128 px/CTA, split-bf16 out) ==========
__global__ void __launch_bounds__(256) proj_qk_kernel(
    const float* __restrict__ x,
    const float* __restrict__ Wq, const float* __restrict__ bq,
    const float* __restrict__ Wk, const float* __restrict__ bk)
{
    __shared__ float sX[32 * 132];
    __shared__ float sW[32 * 68];

    const int tid = threadIdx.x;
    const int g = tid & 31;
    const int h = tid >> 5;
    const int b = blockIdx.y;
    const int n0 = blockIdx.x * 128;
    const bool isq = (h < 4);
    const int dbase = (h & 3) * 8;
    const int woff = (isq ? 0 : 32) + dbase;

    u64 acc[8][2];
#pragma unroll
    for (int i = 0; i < 8; i++) { acc[i][0] = 0; acc[i][1] = 0; }

    for (int c0 = 0; c0 < CH; c0 += 32) {
        __syncthreads();
#pragma unroll
        for (int pass = 0; pass < 4; ++pass) {
            int cc = h + pass * 8;
            const float* src = x + ((size_t)b * CH + c0 + cc) * N_PIX + n0 + g * 4;
            *(float4*)(sX + cc * 132 + g * 4) = *(const float4*)src;
        }
        {
            int d = tid & 31;
            int c4 = (tid >> 5) * 4;
            float4 wq4 = *(const float4*)(Wq + d * CH + c0 + c4);
            float4 wk4 = *(const float4*)(Wk + d * CH + c0 + c4);
            sW[(c4 + 0) * 68 + d] = wq4.x; sW[(c4 + 1) * 68 + d] = wq4.y;
            sW[(c4 + 2) * 68 + d] = wq4.z; sW[(c4 + 3) * 68 + d] = wq4.w;
            sW[(c4 + 0) * 68 + 32 + d] = wk4.x; sW[(c4 + 1) * 68 + 32 + d] = wk4.y;
            sW[(c4 + 2) * 68 + 32 + d] = wk4.z; sW[(c4 + 3) * 68 + 32 + d] = wk4.w;
        }
        __syncthreads();

#pragma unroll 8
        for (int cc = 0; cc < 32; ++cc) {
            float4 xa = *(const float4*)(sX + cc * 132 + g * 4);
            u64 xp0 = pack2(xa.x, xa.y), xp1 = pack2(xa.z, xa.w);
            const float* wp = sW + cc * 68 + woff;
            float4 w0 = *(const float4*)wp;
            float4 w1 = *(const float4*)(wp + 4);
            float wv[8] = {w0.x, w0.y, w0.z, w0.w, w1.x, w1.y, w1.z, w1.w};
#pragma unroll
            for (int i = 0; i < 8; i++) {
                u64 wd = pack2(wv[i], wv[i]);
                acc[i][0] = fma2(wd, xp0, acc[i][0]);
                acc[i][1] = fma2(wd, xp1, acc[i][1]);
            }
        }
    }

    const float* bias = isq ? bq : bk;
    float bb[8];
#pragma unroll
    for (int i = 0; i < 8; i++) bb[i] = bias[dbase + i];
    __nv_bfloat16* oh = (isq ? g_qh : g_kh) + ((size_t)b * N_PIX + n0 + g * 4) * DQK + dbase;
    __nv_bfloat16* ol = (isq ? g_ql : g_kl) + ((size_t)b * N_PIX + n0 + g * 4) * DQK + dbase;
#pragma unroll
    for (int j = 0; j < 4; j++) {
        float v[8];
#pragma unroll
        for (int i = 0; i < 8; i++) {
            float2 t = unpack2(acc[i][j >> 1]);
            v[i] = ((j & 1) ? t.y : t.x) + bb[i];
        }
        u32 hh[4], ll[4];
        split2(v[0], v[1], hh[0], ll[0]);
        split2(v[2], v[3], hh[1], ll[1]);
        split2(v[4], v[5], hh[2], ll[2]);
        split2(v[6], v[7], hh[3], ll[3]);
        *(uint4*)(oh + (size_t)j * DQK) = make_uint4(hh[0], hh[1], hh[2], hh[3]);
        *(uint4*)(ol + (size_t)j * DQK) = make_uint4(ll[0], ll[1], ll[2], ll[3]);
    }
}

// ================== kernel 2: v projection (writes fp16 V) =========================
__global__ void __launch_bounds__(256) proj_v_kernel(
    const float* __restrict__ x, const float* __restrict__ Wv, const float* __restrict__ bv)
{
    __shared__ float sA[32][68];
    __shared__ float sB[32][68];

    int b  = blockIdx.z;
    int n0 = blockIdx.x * 64;
    int d0 = blockIdx.y * 64;
    int tx = threadIdx.x, ty = threadIdx.y, tid = ty * 16 + tx;

    float acc[4][4] = {};

    for (int c0 = 0; c0 < CH; c0 += 32) {
        for (int idx = tid; idx < 512; idx += 256) {
            int r = idx >> 3, q = idx & 7;
            float4 w = *(const float4*)(Wv + (size_t)(d0 + r) * CH + c0 + q * 4);
            sA[q * 4 + 0][r] = w.x; sA[q * 4 + 1][r] = w.y;
            sA[q * 4 + 2][r] = w.z; sA[q * 4 + 3][r] = w.w;

            int r2 = idx >> 4, q2 = idx & 15;
            float4 xv = *(const float4*)(x + ((size_t)b * CH + c0 + r2) * N_PIX + n0 + q2 * 4);
            *(float4*)&sB[r2][q2 * 4] = xv;
        }
        __syncthreads();

#pragma unroll
        for (int k = 0; k < 32; k++) {
            float4 a4 = *(const float4*)&sA[k][ty * 4];
            float4 b4 = *(const float4*)&sB[k][tx * 4];
            float av[4] = {a4.x, a4.y, a4.z, a4.w};
            float bw[4] = {b4.x, b4.y, b4.z, b4.w};
#pragma unroll
            for (int i = 0; i < 4; i++)
#pragma unroll
                for (int j = 0; j < 4; j++)
                    acc[i][j] += av[i] * bw[j];
        }
        __syncthreads();
    }

#pragma unroll
    for (int i = 0; i < 4; i++) {
        int d = d0 + ty * 4 + i;
        float bias = bv[d];
        size_t base = ((size_t)b * CH + d) * N_PIX + n0 + tx * 4;
        __half2 p0 = __floats2half2_rn(acc[i][0] + bias, acc[i][1] + bias);
        __half2 p1 = __floats2half2_rn(acc[i][2] + bias, acc[i][3] + bias);
        uint2 u;
        u.x = *(const u32*)&p0;
        u.y = *(const u32*)&p1;
        *(uint2*)(g_vf + base) = u;
    }
}

// ================== kernel 3: fused attention, fp16 PV + online max ================
// CTA: 128 queries x ALL 256 channels. O^T[n][d] = P[n][m].V; P fp16 in regs.
#define FA_QH   0u           // 128 x 40 halves
#define FA_QL   10240u
#define FA_K    20480u       // 2 bufs x (hi 10240 + lo 10240)
#define FA_KBUF 20480u
#define FA_KLO  10240u
#define FA_V0   61440u       // d-half 0: 128 x 136 halves fp16
#define FA_V1   96256u       // d-half 1
#define FA_STG  61440u       // epilogue staging: 256 x 132 floats (reuses V bufs)
#define FA_SROW 196608u
#define FA_SINV 197120u
#define FA_SMEM 197632u

__global__ void __launch_bounds__(256, 1) fused_attn_kernel(
    const float* __restrict__ x, float* __restrict__ out)
{
    extern __shared__ char sm[];
    const u32 S = smem_u32(sm);

    const int tid = threadIdx.x;
    const int w = tid >> 5, lane = tid & 31;
    const int b  = blockIdx.z;
    const int n0 = blockIdx.x * 128;

    const __nv_bfloat16* qh = g_qh + ((size_t)b * N_PIX + n0) * DQK;
    const __nv_bfloat16* ql = g_ql + ((size_t)b * N_PIX + n0) * DQK;
    const __nv_bfloat16* kh = g_kh + (size_t)b * N_PIX * DQK;
    const __nv_bfloat16* kl = g_kl + (size_t)b * N_PIX * DQK;
    const __half*        vf = g_vf + (size_t)b * CH * N_PIX;

    auto load_q = [&]() {
#pragma unroll
        for (int j = 0; j < 4; ++j) {
            int idx = tid + j * 256;
            int mat = idx >> 9;
            int within = idx & 511;
            int row = within >> 2, c = within & 3;
            const __nv_bfloat16* src = (mat ? ql : qh) + (size_t)row * DQK + c * 8;
            cp16(S + FA_QH + (u32)mat * 10240u + (u32)(row * 40 + c * 8) * 2, src);
        }
    };
    auto load_k = [&](int t2, u32 kbuf) {
#pragma unroll
        for (int j = 0; j < 4; ++j) {
            int idx = tid + j * 256;
            int mat = idx >> 9;
            int within = idx & 511;
            int row = within >> 2, c = within & 3;
            const __nv_bfloat16* src = (mat ? kl : kh) + ((size_t)t2 * 128 + row) * DQK + c * 8;
            cp16(kbuf + (u32)mat * FA_KLO + (u32)(row * 40 + c * 8) * 2, src);
        }
    };
    auto load_v = [&](int m0, int hf) {
        const u32 vb = S + (hf ? FA_V1 : FA_V0);
#pragma unroll
        for (int j = 0; j < 8; ++j) {
            int idx = tid + j * 256;          // 0..2047
            int row = idx >> 4, c = idx & 15;
            const __half* src = vf + ((size_t)(hf * 128 + row)) * N_PIX + m0 + c * 8;
            cp16(vb + (u32)(row * 136 + c * 8) * 2, src);
        }
    };

    // ---- prologue: G1 = Q + K(0);  G2 = V(0,h0);  G3 = V(0,h1) + K(1) ----
    load_q(); load_k(0, S + FA_K); CP_COMMIT();
    load_v(0, 0); CP_COMMIT();
    load_v(0, 1); load_k(1, S + FA_K + FA_KBUF); CP_COMMIT();

    float accO[32][4];
#pragma unroll
    for (int i = 0; i < 32; i++)
#pragma unroll
        for (int q = 0; q < 4; q++) accO[i][q] = 0.f;
    float rs0 = 0.f, rs1 = 0.f;
    float M0 = -1e30f, M1 = -1e30f;   // running row maxima

    const int arow = w * 16 + (lane & 15);
    const int acol = (lane >> 4) << 3;
    const int brow = (lane & 7) + ((lane >> 4) & 1) * 8;
    const int bcol = ((lane >> 3) & 1) * 8;

    const int NT = N_PIX / 128;  // 32 m-tiles
    for (int t = 0; t < NT; ++t) {
        CP_WAIT2();               // K(t) retired
        __syncthreads();

        // ---- E phase: E[128n x 128m] = Q.K^T, 3-term split-bf16 ----
        const u32 kb = S + FA_K + (u32)(t & 1) * FA_KBUF;
        float accE[16][4];
#pragma unroll
        for (int i = 0; i < 16; i++)
#pragma unroll
            for (int q = 0; q < 4; q++) accE[i][q] = 0.f;

#pragma unroll
        for (int kk = 0; kk < 32; kk += 16) {
            u32 ah[4], al[4];
            u32 ao = (u32)(arow * 40 + acol + kk) * 2;
            ldm4(S + FA_QH + ao, ah[0], ah[1], ah[2], ah[3]);
            ldm4(S + FA_QL + ao, al[0], al[1], al[2], al[3]);
#pragma unroll
            for (int nf = 0; nf < 8; nf++) {
                u32 bo = (u32)((nf * 16 + brow) * 40 + bcol + kk) * 2;
                u32 bh[4], bl[4];
                ldm4(kb + bo, bh[0], bh[1], bh[2], bh[3]);
                ldm4(kb + FA_KLO + bo, bl[0], bl[1], bl[2], bl[3]);
                mma16816(accE[nf * 2],     ah, bh[0], bh[1]);
                mma16816(accE[nf * 2],     ah, bl[0], bl[1]);
                mma16816(accE[nf * 2],     al, bh[0], bh[1]);
                mma16816(accE[nf * 2 + 1], ah, bh[2], bh[3]);
                mma16816(accE[nf * 2 + 1], ah, bl[2], bl[3]);
                mma16816(accE[nf * 2 + 1], al, bh[2], bh[3]);
            }
        }

        // ---- online max: tile row max, rescale accumulators ----
        float tm0 = -1e30f, tm1 = -1e30f;
#pragma unroll
        for (int i = 0; i < 16; i++) {
            tm0 = fmaxf(tm0, fmaxf(accE[i][0], accE[i][1]));
            tm1 = fmaxf(tm1, fmaxf(accE[i][2], accE[i][3]));
        }
        tm0 = fmaxf(tm0, __shfl_xor_sync(0xffffffffu, tm0, 1));
        tm0 = fmaxf(tm0, __shfl_xor_sync(0xffffffffu, tm0, 2));
        tm1 = fmaxf(tm1, __shfl_xor_sync(0xffffffffu, tm1, 1));
        tm1 = fmaxf(tm1, __shfl_xor_sync(0xffffffffu, tm1, 2));
        float nM0 = fmaxf(M0, tm0), nM1 = fmaxf(M1, tm1);
        float sc0 = __expf(M0 - nM0), sc1 = __expf(M1 - nM1);
        M0 = nM0; M1 = nM1;
        rs0 *= sc0; rs1 *= sc1;
#pragma unroll
        for (int i = 0; i < 32; i++) {
            accO[i][0] *= sc0; accO[i][1] *= sc0;
            accO[i][2] *= sc1; accO[i][3] *= sc1;
        }

        // ---- exp + fp16 P fragments + rowsum from ROUNDED P ----
        u32 pa[8][4];
#pragma unroll
        for (int ks = 0; ks < 8; ks++) {
            float e00 = __expf(accE[2 * ks][0] - M0);
            float e01 = __expf(accE[2 * ks][1] - M0);
            float e02 = __expf(accE[2 * ks][2] - M1);
            float e03 = __expf(accE[2 * ks][3] - M1);
            float e10 = __expf(accE[2 * ks + 1][0] - M0);
            float e11 = __expf(accE[2 * ks + 1][1] - M0);
            float e12 = __expf(accE[2 * ks + 1][2] - M1);
            float e13 = __expf(accE[2 * ks + 1][3] - M1);
            __half2 h0 = __floats2half2_rn(e00, e01);   // a0: (r,   k0..1)
            __half2 h1 = __floats2half2_rn(e02, e03);   // a1: (r+8, k0..1)
            __half2 h2 = __floats2half2_rn(e10, e11);   // a2: (r,   k8..9)
            __half2 h3 = __floats2half2_rn(e12, e13);   // a3: (r+8, k8..9)
            pa[ks][0] = *(const u32*)&h0;
            pa[ks][1] = *(const u32*)&h1;
            pa[ks][2] = *(const u32*)&h2;
            pa[ks][3] = *(const u32*)&h3;
            float2 f0 = __half22float2(h0);
            float2 f1 = __half22float2(h1);
            float2 f2 = __half22float2(h2);
            float2 f3 = __half22float2(h3);
            rs0 += (f0.x + f0.y) + (f2.x + f2.y);
            rs1 += (f1.x + f1.y) + (f3.x + f3.y);
        }

        // ---- PV half 0 (d 0..127) ----
        CP_WAIT1();               // V(t,h0) retired
        __syncthreads();
        {
            const u32 vb = S + FA_V0;
#pragma unroll
            for (int ks = 0; ks < 8; ks++) {
#pragma unroll
                for (int dg = 0; dg < 8; dg++) {
                    u32 boff = (u32)((dg * 16 + brow) * 136 + bcol + ks * 16) * 2;
                    u32 b0, b1, b2, b3;
                    ldm4(vb + boff, b0, b1, b2, b3);
                    mma16816h(accO[dg * 2],     pa[ks], b0, b1);
                    mma16816h(accO[dg * 2 + 1], pa[ks], b2, b3);
                }
            }
        }
        __syncthreads();          // all warps done reading V0
        {
            int tv = (t + 1 < NT) ? t + 1 : NT - 1;
            load_v(tv * 128, 0);
            CP_COMMIT();
        }

        // ---- PV half 1 (d 128..255) ----
        CP_WAIT1();               // V(t,h1)+K(t+1) retired
        __syncthreads();
        {
            const u32 vb = S + FA_V1;
#pragma unroll
            for (int ks = 0; ks < 8; ks++) {
#pragma unroll
                for (int dg = 0; dg < 8; dg++) {
                    u32 boff = (u32)((dg * 16 + brow) * 136 + bcol + ks * 16) * 2;
                    u32 b0, b1, b2, b3;
                    ldm4(vb + boff, b0, b1, b2, b3);
                    mma16816h(accO[16 + dg * 2],     pa[ks], b0, b1);
                    mma16816h(accO[16 + dg * 2 + 1], pa[ks], b2, b3);
                }
            }
        }
        __syncthreads();          // all warps done reading V1
        {
            int tv = (t + 1 < NT) ? t + 1 : NT - 1;
            int tk = (t + 2 < NT) ? t + 2 : NT - 1;
            load_v(tv * 128, 1);
            load_k(tk, S + FA_K + (u32)(t & 1) * FA_KBUF);
            CP_COMMIT();
        }
    }

    // drain pending dummy copies before reusing V smem as staging
    CP_WAIT0();
    __syncthreads();

    // ---- row sums: quad-reduce, then -> 1/sum ----
    rs0 += __shfl_xor_sync(0xffffffffu, rs0, 1);
    rs0 += __shfl_xor_sync(0xffffffffu, rs0, 2);
    rs1 += __shfl_xor_sync(0xffffffffu, rs1, 1);
    rs1 += __shfl_xor_sync(0xffffffffu, rs1, 2);
    if ((lane & 3) == 0) {
        ((float*)(sm + FA_SROW))[w * 16 + (lane >> 2)] = rs0;
        ((float*)(sm + FA_SROW))[w * 16 + (lane >> 2) + 8] = rs1;
    }
    __syncthreads();
    if (tid < 128)
        ((float*)(sm + FA_SINV))[tid] = 1.0f / ((float*)(sm + FA_SROW))[tid];
    __syncthreads();

    // ---- epilogue phase 1: O^T regs -> staging smem [d][n], scaled by rinv[n] ----
    {
        float* stg = (float*)(sm + FA_STG);
        const float* sinv = (const float*)(sm + FA_SINV);
        const int er = lane >> 2;
        const int ec = 2 * (lane & 3);
        const int n = w * 16 + er;
        const float s0 = sinv[n];
        const float s1 = sinv[n + 8];
#pragma unroll
        for (int idx = 0; idx < 32; idx++) {
            const int hf = idx >> 4, rem = idx & 15;
            const int dg = rem >> 1, f = rem & 1;
            const int d = hf * 128 + dg * 16 + f * 8 + ec;
            stg[d * 132 + n]           = accO[idx][0] * s0;
            stg[(d + 1) * 132 + n]     = accO[idx][1] * s0;
            stg[d * 132 + n + 8]       = accO[idx][2] * s1;
            stg[(d + 1) * 132 + n + 8] = accO[idx][3] * s1;
        }
    }
    __syncthreads();

    // ---- epilogue phase 2: coalesced out = stg + x ----
    {
        const float* stg = (const float*)(sm + FA_STG);
        const int dl = tid >> 5;
        const int nn = (tid & 31) * 4;
#pragma unroll 4
        for (int it = 0; it < 32; it++) {
            const int d = it * 8 + dl;
            float4 v = *(const float4*)&stg[d * 132 + nn];
            size_t go = ((size_t)b * CH + d) * N_PIX + n0 + nn;
            float4 xv = *(const float4*)(x + go);
            *(float4*)(out + go) = make_float4(v.x + xv.x, v.y + xv.y,
                                               v.z + xv.z, v.w + xv.w);
        }
    }
}

// ================== launch =========================================================
extern "C" void kernel_launch(void* const* d_in, const int* in_sizes, int n_in,
                              void* d_out, int out_size)
{
    (void)in_sizes; (void)n_in; (void)out_size;
    const float* x  = (const float*)d_in[0];
    const float* Wq = (const float*)d_in[1];
    const float* bq = (const float*)d_in[2];
    const float* Wk = (const float*)d_in[3];
    const float* bk = (const float*)d_in[4];
    const float* Wv = (const float*)d_in[5];
    const float* bv = (const float*)d_in[6];
    float* out = (float*)d_out;

    static int smem_set = 0;
    if (!smem_set) {
        cudaFuncSetAttribute(fused_attn_kernel,
                             cudaFuncAttributeMaxDynamicSharedMemorySize, FA_SMEM);
        smem_set = 1;
    }

    dim3 blk2(16, 16);
    proj_qk_kernel<<<dim3(32, 4), 256>>>(x, Wq, bq, Wk, bk);
    proj_v_kernel<<<dim3(64, 4, 4), blk2>>>(x, Wv, bv);
    fused_attn_kernel<<<dim3(32, 1, 4), 256, FA_SMEM>>>(x, out);
}

// round 12
// speedup vs baseline: 2.7046x; 1.1954x over previous
#include <cuda_runtime.h>
#include <cuda_bf16.h>
#include <cuda_fp16.h>
#include <cstdint>

#define N_PIX 4096
#define BATCH 4
#define CH    256
#define DQK   32

typedef unsigned long long u64;
typedef unsigned int u32;

// ---------------- scratch (device globals) ------------------------------------------
__device__ __nv_bfloat16 g_qh[(size_t)BATCH * N_PIX * DQK];  // Q hi [b][n][32]
__device__ __nv_bfloat16 g_ql[(size_t)BATCH * N_PIX * DQK];  // Q lo
__device__ __nv_bfloat16 g_kh[(size_t)BATCH * N_PIX * DQK];  // K hi [b][m][32]
__device__ __nv_bfloat16 g_kl[(size_t)BATCH * N_PIX * DQK];  // K lo
__device__ __half        g_vf[(size_t)BATCH * CH * N_PIX];   // V fp16 [b][d][m]

// ---------------- f32x2 helpers ------------------------------------------------------
__device__ __forceinline__ u64 fma2(u64 a, u64 b, u64 c) {
    u64 d;
    asm("fma.rn.f32x2 %0, %1, %2, %3;" : "=l"(d) : "l"(a), "l"(b), "l"(c));
    return d;
}
__device__ __forceinline__ u64 pack2(float x, float y) {
    u64 r;
    asm("mov.b64 %0, {%1, %2};" : "=l"(r) : "f"(x), "f"(y));
    return r;
}
__device__ __forceinline__ float2 unpack2(u64 v) {
    float2 r;
    asm("mov.b64 {%0, %1}, %2;" : "=f"(r.x), "=f"(r.y) : "l"(v));
    return r;
}

// ---------------- split-bf16 helper ---------------------------------------------------
__device__ __forceinline__ void split2(float a, float b, u32& hi, u32& lo) {
    __nv_bfloat162 h = __floats2bfloat162_rn(a, b);
    u32 hraw = *(const u32*)&h;
    float ha = __uint_as_float(hraw << 16);
    float hb = __uint_as_float(hraw & 0xFFFF0000u);
    __nv_bfloat162 l = __floats2bfloat162_rn(a - ha, b - hb);
    hi = hraw;
    lo = *(const u32*)&l;
}

// ---------------- smem / cp.async / mma helpers -------------------------------------
__device__ __forceinline__ u32 smem_u32(const void* p) {
    u32 a;
    asm("{ .reg .u64 t; cvta.to.shared.u64 t, %1; cvt.u32.u64 %0, t; }" : "=r"(a) : "l"(p));
    return a;
}
__device__ __forceinline__ void cp16(u32 d, const void* s) {
    asm volatile("cp.async.cg.shared.global [%0], [%1], 16;" :: "r"(d), "l"(s));
}
#define CP_COMMIT() asm volatile("cp.async.commit_group;" ::: "memory")
#define CP_WAIT2()  asm volatile("cp.async.wait_group 2;" ::: "memory")
#define CP_WAIT1()  asm volatile("cp.async.wait_group 1;" ::: "memory")
#define CP_WAIT0()  asm volatile("cp.async.wait_group 0;" ::: "memory")

__device__ __forceinline__ void ldm4(u32 addr, u32& r0, u32& r1, u32& r2, u32& r3) {
    asm volatile("ldmatrix.sync.aligned.m8n8.x4.shared.b16 {%0,%1,%2,%3}, [%4];"
                 : "=r"(r0), "=r"(r1), "=r"(r2), "=r"(r3) : "r"(addr));
}
__device__ __forceinline__ void ldm4t(u32 addr, u32& r0, u32& r1, u32& r2, u32& r3) {
    asm volatile("ldmatrix.sync.aligned.m8n8.x4.trans.shared.b16 {%0,%1,%2,%3}, [%4];"
                 : "=r"(r0), "=r"(r1), "=r"(r2), "=r"(r3) : "r"(addr));
}
// bf16 MMA
__device__ __forceinline__ void mma16816(float* c, const u32* a, u32 b0, u32 b1) {
    asm volatile(
        "mma.sync.aligned.m16n8k16.row.col.f32.bf16.bf16.f32 "
        "{%0,%1,%2,%3}, {%4,%5,%6,%7}, {%8,%9}, {%0,%1,%2,%3};"
        : "+f"(c[0]), "+f"(c[1]), "+f"(c[2]), "+f"(c[3])
        : "r"(a[0]), "r"(a[1]), "r"(a[2]), "r"(a[3]), "r"(b0), "r"(b1));
}
// fp16 MMA
__device__ __forceinline__ void mma16816h(float* c, const u32* a, u32 b0, u32 b1) {
    asm volatile(
        "mma.sync.aligned.m16n8k16.row.col.f32.f16.f16.f32 "
        "{%0,%1,%2,%3}, {%4,%5,%6,%7}, {%8,%9}, {%0,%1,%2,%3};"
        : "+f"(c[0]), "+f"(c[1]), "+f"(c[2]), "+f"(c[3])
        : "r"(a[0]), "r"(a[1]), "r"(a[2]), "r"(a[3]), "r"(b0), "r"(b1));
}
__device__ __forceinline__ u32 ex2h2(u32 z) {
    asm("ex2.approx.f16x2 %0, %0;" : "+r"(z));
    return z;
}

// ================== kernel 1: q/k projection (128 px/CTA, split-bf16 out) ==========
__global__ void __launch_bounds__(256) proj_qk_kernel(
    const float* __restrict__ x,
    const float* __restrict__ Wq, const float* __restrict__ bq,
    const float* __restrict__ Wk, const float* __restrict__ bk)
{
    __shared__ float sX[32 * 132];
    __shared__ float sW[32 * 68];

    const int tid = threadIdx.x;
    const int g = tid & 31;
    const int h = tid >> 5;
    const int b = blockIdx.y;
    const int n0 = blockIdx.x * 128;
    const bool isq = (h < 4);
    const int dbase = (h & 3) * 8;
    const int woff = (isq ? 0 : 32) + dbase;

    u64 acc[8][2];
#pragma unroll
    for (int i = 0; i < 8; i++) { acc[i][0] = 0; acc[i][1] = 0; }

    for (int c0 = 0; c0 < CH; c0 += 32) {
        __syncthreads();
#pragma unroll
        for (int pass = 0; pass < 4; ++pass) {
            int cc = h + pass * 8;
            const float* src = x + ((size_t)b * CH + c0 + cc) * N_PIX + n0 + g * 4;
            *(float4*)(sX + cc * 132 + g * 4) = *(const float4*)src;
        }
        {
            int d = tid & 31;
            int c4 = (tid >> 5) * 4;
            float4 wq4 = *(const float4*)(Wq + d * CH + c0 + c4);
            float4 wk4 = *(const float4*)(Wk + d * CH + c0 + c4);
            sW[(c4 + 0) * 68 + d] = wq4.x; sW[(c4 + 1) * 68 + d] = wq4.y;
            sW[(c4 + 2) * 68 + d] = wq4.z; sW[(c4 + 3) * 68 + d] = wq4.w;
            sW[(c4 + 0) * 68 + 32 + d] = wk4.x; sW[(c4 + 1) * 68 + 32 + d] = wk4.y;
            sW[(c4 + 2) * 68 + 32 + d] = wk4.z; sW[(c4 + 3) * 68 + 32 + d] = wk4.w;
        }
        __syncthreads();

#pragma unroll 8
        for (int cc = 0; cc < 32; ++cc) {
            float4 xa = *(const float4*)(sX + cc * 132 + g * 4);
            u64 xp0 = pack2(xa.x, xa.y), xp1 = pack2(xa.z, xa.w);
            const float* wp = sW + cc * 68 + woff;
            float4 w0 = *(const float4*)wp;
            float4 w1 = *(const float4*)(wp + 4);
            float wv[8] = {w0.x, w0.y, w0.z, w0.w, w1.x, w1.y, w1.z, w1.w};
#pragma unroll
            for (int i = 0; i < 8; i++) {
                u64 wd = pack2(wv[i], wv[i]);
                acc[i][0] = fma2(wd, xp0, acc[i][0]);
                acc[i][1] = fma2(wd, xp1, acc[i][1]);
            }
        }
    }

    const float* bias = isq ? bq : bk;
    float bb[8];
#pragma unroll
    for (int i = 0; i < 8; i++) bb[i] = bias[dbase + i];
    __nv_bfloat16* oh = (isq ? g_qh : g_kh) + ((size_t)b * N_PIX + n0 + g * 4) * DQK + dbase;
    __nv_bfloat16* ol = (isq ? g_ql : g_kl) + ((size_t)b * N_PIX + n0 + g * 4) * DQK + dbase;
#pragma unroll
    for (int j = 0; j < 4; j++) {
        float v[8];
#pragma unroll
        for (int i = 0; i < 8; i++) {
            float2 t = unpack2(acc[i][j >> 1]);
            v[i] = ((j & 1) ? t.y : t.x) + bb[i];
        }
        u32 hh[4], ll[4];
        split2(v[0], v[1], hh[0], ll[0]);
        split2(v[2], v[3], hh[1], ll[1]);
        split2(v[4], v[5], hh[2], ll[2]);
        split2(v[6], v[7], hh[3], ll[3]);
        *(uint4*)(oh + (size_t)j * DQK) = make_uint4(hh[0], hh[1], hh[2], hh[3]);
        *(uint4*)(ol + (size_t)j * DQK) = make_uint4(ll[0], ll[1], ll[2], ll[3]);
    }
}

// ================== kernel 2: v projection on tensor cores =========================
// V[d][m] = sum_c Wv[d][c] x[c][m] + bv[d], fp16 out. CTA tile 128d x 128m, K=256.
__global__ void __launch_bounds__(256) proj_v_kernel(
    const float* __restrict__ x, const float* __restrict__ Wv, const float* __restrict__ bv)
{
    __shared__ __align__(16) __nv_bfloat16 sWh[128 * 40];
    __shared__ __align__(16) __nv_bfloat16 sWl[128 * 40];
    __shared__ __align__(16) __nv_bfloat16 sXh[32 * 136];
    __shared__ __align__(16) __nv_bfloat16 sXl[32 * 136];

    const int tid = threadIdx.x;
    const int w = tid >> 5, lane = tid & 31;
    const int b  = blockIdx.z;
    const int d0 = blockIdx.y * 128;
    const int m0 = blockIdx.x * 128;

    float accV[16][4];
#pragma unroll
    for (int i = 0; i < 16; i++)
#pragma unroll
        for (int q = 0; q < 4; q++) accV[i][q] = 0.f;

    const int arow = w * 16 + (lane & 15);
    const int acol = (lane >> 4) << 3;
    // trans-B addressing (x stored [c][m], loaded as x^T[m][c] frags)
    const int brow_c = (lane & 7) + ((lane >> 3) & 1) * 8;
    const int bcol_m = ((lane >> 4) & 1) * 8;

    const u32 SWH = smem_u32(sWh), SWL = smem_u32(sWl);
    const u32 SXH = smem_u32(sXh), SXL = smem_u32(sXl);

    for (int c0 = 0; c0 < CH; c0 += 32) {
        __syncthreads();
        // W chunk [128 d][32 c] -> split-bf16, pitch 40
#pragma unroll
        for (int j = 0; j < 4; j++) {
            int idx = tid + j * 256;
            int d = idx >> 3, c4 = (idx & 7) * 4;
            float4 wv4 = *(const float4*)(Wv + (size_t)(d0 + d) * CH + c0 + c4);
            u32 h0, l0, h1, l1;
            split2(wv4.x, wv4.y, h0, l0);
            split2(wv4.z, wv4.w, h1, l1);
            *(uint2*)&sWh[d * 40 + c4] = make_uint2(h0, h1);
            *(uint2*)&sWl[d * 40 + c4] = make_uint2(l0, l1);
        }
        // x chunk [32 c][128 m] -> split-bf16, pitch 136 (natural orientation)
#pragma unroll
        for (int j = 0; j < 4; j++) {
            int idx = tid + j * 256;
            int c = idx >> 5, m4 = (idx & 31) * 4;
            float4 xv4 = *(const float4*)(x + ((size_t)b * CH + c0 + c) * N_PIX + m0 + m4);
            u32 h0, l0, h1, l1;
            split2(xv4.x, xv4.y, h0, l0);
            split2(xv4.z, xv4.w, h1, l1);
            *(uint2*)&sXh[c * 136 + m4] = make_uint2(h0, h1);
            *(uint2*)&sXl[c * 136 + m4] = make_uint2(l0, l1);
        }
        __syncthreads();

#pragma unroll
        for (int kk = 0; kk < 32; kk += 16) {
            u32 ah[4], al[4];
            u32 ao = (u32)(arow * 40 + acol + kk) * 2;
            ldm4(SWH + ao, ah[0], ah[1], ah[2], ah[3]);
            ldm4(SWL + ao, al[0], al[1], al[2], al[3]);
#pragma unroll
            for (int mb = 0; mb < 8; mb++) {
                u32 boff = (u32)((kk + brow_c) * 136 + mb * 16 + bcol_m) * 2;
                u32 bh[4], bl[4];
                ldm4t(SXH + boff, bh[0], bh[1], bh[2], bh[3]);
                ldm4t(SXL + boff, bl[0], bl[1], bl[2], bl[3]);
                mma16816(accV[mb * 2],     ah, bh[0], bh[1]);
                mma16816(accV[mb * 2],     ah, bl[0], bl[1]);
                mma16816(accV[mb * 2],     al, bh[0], bh[1]);
                mma16816(accV[mb * 2 + 1], ah, bh[2], bh[3]);
                mma16816(accV[mb * 2 + 1], ah, bl[2], bl[3]);
                mma16816(accV[mb * 2 + 1], al, bh[2], bh[3]);
            }
        }
    }

    // epilogue: add bias, convert fp16, store
    const int er = lane >> 2, ec = 2 * (lane & 3);
    const int dA = d0 + w * 16 + er;
    const int dB = dA + 8;
    const float biasA = bv[dA], biasB = bv[dB];
#pragma unroll
    for (int mb = 0; mb < 8; mb++) {
#pragma unroll
        for (int hf = 0; hf < 2; hf++) {
            const float* c = accV[mb * 2 + hf];
            int m = m0 + mb * 16 + hf * 8 + ec;
            __half2 vA = __floats2half2_rn(c[0] + biasA, c[1] + biasA);
            __half2 vB = __floats2half2_rn(c[2] + biasB, c[3] + biasB);
            *(u32*)&g_vf[((size_t)b * CH + dA) * N_PIX + m] = *(const u32*)&vA;
            *(u32*)&g_vf[((size_t)b * CH + dB) * N_PIX + m] = *(const u32*)&vB;
        }
    }
}

// ================== kernel 3: fused attention, fp16 PV + online max ================
#define FA_QH   0u
#define FA_QL   10240u
#define FA_K    20480u
#define FA_KBUF 20480u
#define FA_KLO  10240u
#define FA_V0   61440u
#define FA_V1   96256u
#define FA_STG  61440u
#define FA_SROW 196608u
#define FA_SINV 197120u
#define FA_SMEM 197632u

__global__ void __launch_bounds__(256, 1) fused_attn_kernel(
    const float* __restrict__ x, float* __restrict__ out)
{
    extern __shared__ char sm[];
    const u32 S = smem_u32(sm);

    const int tid = threadIdx.x;
    const int w = tid >> 5, lane = tid & 31;
    const int b  = blockIdx.z;
    const int n0 = blockIdx.x * 128;

    const __nv_bfloat16* qh = g_qh + ((size_t)b * N_PIX + n0) * DQK;
    const __nv_bfloat16* ql = g_ql + ((size_t)b * N_PIX + n0) * DQK;
    const __nv_bfloat16* kh = g_kh + (size_t)b * N_PIX * DQK;
    const __nv_bfloat16* kl = g_kl + (size_t)b * N_PIX * DQK;
    const __half*        vf = g_vf + (size_t)b * CH * N_PIX;

    auto load_q = [&]() {
#pragma unroll
        for (int j = 0; j < 4; ++j) {
            int idx = tid + j * 256;
            int mat = idx >> 9;
            int within = idx & 511;
            int row = within >> 2, c = within & 3;
            const __nv_bfloat16* src = (mat ? ql : qh) + (size_t)row * DQK + c * 8;
            cp16(S + FA_QH + (u32)mat * 10240u + (u32)(row * 40 + c * 8) * 2, src);
        }
    };
    auto load_k = [&](int t2, u32 kbuf) {
#pragma unroll
        for (int j = 0; j < 4; ++j) {
            int idx = tid + j * 256;
            int mat = idx >> 9;
            int within = idx & 511;
            int row = within >> 2, c = within & 3;
            const __nv_bfloat16* src = (mat ? kl : kh) + ((size_t)t2 * 128 + row) * DQK + c * 8;
            cp16(kbuf + (u32)mat * FA_KLO + (u32)(row * 40 + c * 8) * 2, src);
        }
    };
    auto load_v = [&](int m0, int hf) {
        const u32 vb = S + (hf ? FA_V1 : FA_V0);
#pragma unroll
        for (int j = 0; j < 8; ++j) {
            int idx = tid + j * 256;
            int row = idx >> 4, c = idx & 15;
            const __half* src = vf + ((size_t)(hf * 128 + row)) * N_PIX + m0 + c * 8;
            cp16(vb + (u32)(row * 136 + c * 8) * 2, src);
        }
    };

    // ---- prologue ----
    load_q(); load_k(0, S + FA_K); CP_COMMIT();
    load_v(0, 0); CP_COMMIT();
    load_v(0, 1); load_k(1, S + FA_K + FA_KBUF); CP_COMMIT();

    float accO[32][4];
#pragma unroll
    for (int i = 0; i < 32; i++)
#pragma unroll
        for (int q = 0; q < 4; q++) accO[i][q] = 0.f;
    float accRS[4] = {0.f, 0.f, 0.f, 0.f};
    float M0 = -1e30f, M1 = -1e30f;

    const int arow = w * 16 + (lane & 15);
    const int acol = (lane >> 4) << 3;
    const int brow = (lane & 7) + ((lane >> 4) & 1) * 8;
    const int bcol = ((lane >> 3) & 1) * 8;
    const u32 ONESH2 = 0x3C003C00u;           // fp16 {1,1}
    const float L2E = 1.4426950408889634f;

    const int NT = N_PIX / 128;
    for (int t = 0; t < NT; ++t) {
        CP_WAIT2();
        __syncthreads();

        // ---- E phase ----
        const u32 kb = S + FA_K + (u32)(t & 1) * FA_KBUF;
        float accE[16][4];
#pragma unroll
        for (int i = 0; i < 16; i++)
#pragma unroll
            for (int q = 0; q < 4; q++) accE[i][q] = 0.f;

#pragma unroll
        for (int kk = 0; kk < 32; kk += 16) {
            u32 ah[4], al[4];
            u32 ao = (u32)(arow * 40 + acol + kk) * 2;
            ldm4(S + FA_QH + ao, ah[0], ah[1], ah[2], ah[3]);
            ldm4(S + FA_QL + ao, al[0], al[1], al[2], al[3]);
#pragma unroll
            for (int nf = 0; nf < 8; nf++) {
                u32 bo = (u32)((nf * 16 + brow) * 40 + bcol + kk) * 2;
                u32 bh[4], bl[4];
                ldm4(kb + bo, bh[0], bh[1], bh[2], bh[3]);
                ldm4(kb + FA_KLO + bo, bl[0], bl[1], bl[2], bl[3]);
                mma16816(accE[nf * 2],     ah, bh[0], bh[1]);
                mma16816(accE[nf * 2],     ah, bl[0], bl[1]);
                mma16816(accE[nf * 2],     al, bh[0], bh[1]);
                mma16816(accE[nf * 2 + 1], ah, bh[2], bh[3]);
                mma16816(accE[nf * 2 + 1], ah, bl[2], bl[3]);
                mma16816(accE[nf * 2 + 1], al, bh[2], bh[3]);
            }
        }

        // ---- online max + guarded rescale ----
        float tm0 = -1e30f, tm1 = -1e30f;
#pragma unroll
        for (int i = 0; i < 16; i++) {
            tm0 = fmaxf(tm0, fmaxf(accE[i][0], accE[i][1]));
            tm1 = fmaxf(tm1, fmaxf(accE[i][2], accE[i][3]));
        }
        tm0 = fmaxf(tm0, __shfl_xor_sync(0xffffffffu, tm0, 1));
        tm0 = fmaxf(tm0, __shfl_xor_sync(0xffffffffu, tm0, 2));
        tm1 = fmaxf(tm1, __shfl_xor_sync(0xffffffffu, tm1, 1));
        tm1 = fmaxf(tm1, __shfl_xor_sync(0xffffffffu, tm1, 2));
        float nM0 = fmaxf(M0, tm0), nM1 = fmaxf(M1, tm1);
        if (__any_sync(0xffffffffu, (nM0 > M0) || (nM1 > M1))) {
            float sc0 = __expf(M0 - nM0), sc1 = __expf(M1 - nM1);
#pragma unroll
            for (int i = 0; i < 32; i++) {
                accO[i][0] *= sc0; accO[i][1] *= sc0;
                accO[i][2] *= sc1; accO[i][3] *= sc1;
            }
            accRS[0] *= sc0; accRS[2] *= sc1;
        }
        M0 = nM0; M1 = nM1;

        // ---- exp via ex2.approx.f16x2, P frags in fp16 regs ----
        u32 pa[8][4];
        const float zb0 = -M0 * L2E, zb1 = -M1 * L2E;
#pragma unroll
        for (int ks = 0; ks < 8; ks++) {
            float z00 = fmaf(accE[2 * ks][0], L2E, zb0);
            float z01 = fmaf(accE[2 * ks][1], L2E, zb0);
            float z02 = fmaf(accE[2 * ks][2], L2E, zb1);
            float z03 = fmaf(accE[2 * ks][3], L2E, zb1);
            float z10 = fmaf(accE[2 * ks + 1][0], L2E, zb0);
            float z11 = fmaf(accE[2 * ks + 1][1], L2E, zb0);
            float z12 = fmaf(accE[2 * ks + 1][2], L2E, zb1);
            float z13 = fmaf(accE[2 * ks + 1][3], L2E, zb1);
            __half2 h0 = __floats2half2_rn(z00, z01);
            __half2 h1 = __floats2half2_rn(z02, z03);
            __half2 h2 = __floats2half2_rn(z10, z11);
            __half2 h3 = __floats2half2_rn(z12, z13);
            pa[ks][0] = ex2h2(*(const u32*)&h0);
            pa[ks][1] = ex2h2(*(const u32*)&h1);
            pa[ks][2] = ex2h2(*(const u32*)&h2);
            pa[ks][3] = ex2h2(*(const u32*)&h3);
        }
        // rowsum of rounded P via ones-MMA (tensor pipe, overlaps V wait)
#pragma unroll
        for (int ks = 0; ks < 8; ks++)
            mma16816h(accRS, pa[ks], ONESH2, ONESH2);

        // ---- PV half 0 (d 0..127) ----
        CP_WAIT1();
        __syncthreads();
        {
            const u32 vb = S + FA_V0;
#pragma unroll
            for (int ks = 0; ks < 8; ks++) {
#pragma unroll
                for (int dg = 0; dg < 8; dg++) {
                    u32 boff = (u32)((dg * 16 + brow) * 136 + bcol + ks * 16) * 2;
                    u32 b0, b1, b2, b3;
                    ldm4(vb + boff, b0, b1, b2, b3);
                    mma16816h(accO[dg * 2],     pa[ks], b0, b1);
                    mma16816h(accO[dg * 2 + 1], pa[ks], b2, b3);
                }
            }
        }
        __syncthreads();
        {
            int tv = (t + 1 < NT) ? t + 1 : NT - 1;
            load_v(tv * 128, 0);
            CP_COMMIT();
        }

        // ---- PV half 1 (d 128..255) ----
        CP_WAIT1();
        __syncthreads();
        {
            const u32 vb = S + FA_V1;
#pragma unroll
            for (int ks = 0; ks < 8; ks++) {
#pragma unroll
                for (int dg = 0; dg < 8; dg++) {
                    u32 boff = (u32)((dg * 16 + brow) * 136 + bcol + ks * 16) * 2;
                    u32 b0, b1, b2, b3;
                    ldm4(vb + boff, b0, b1, b2, b3);
                    mma16816h(accO[16 + dg * 2],     pa[ks], b0, b1);
                    mma16816h(accO[16 + dg * 2 + 1], pa[ks], b2, b3);
                }
            }
        }
        __syncthreads();
        {
            int tv = (t + 1 < NT) ? t + 1 : NT - 1;
            int tk = (t + 2 < NT) ? t + 2 : NT - 1;
            load_v(tv * 128, 1);
            load_k(tk, S + FA_K + (u32)(t & 1) * FA_KBUF);
            CP_COMMIT();
        }
    }

    CP_WAIT0();
    __syncthreads();

    // ---- row sums -> 1/sum (accRS holds complete row sums; quad-identical) ----
    if ((lane & 3) == 0) {
        ((float*)(sm + FA_SROW))[w * 16 + (lane >> 2)] = accRS[0];
        ((float*)(sm + FA_SROW))[w * 16 + (lane >> 2) + 8] = accRS[2];
    }
    __syncthreads();
    if (tid < 128)
        ((float*)(sm + FA_SINV))[tid] = 1.0f / ((float*)(sm + FA_SROW))[tid];
    __syncthreads();

    // ---- epilogue phase 1: O^T regs -> staging smem [d][n], scaled by rinv[n] ----
    {
        float* stg = (float*)(sm + FA_STG);
        const float* sinv = (const float*)(sm + FA_SINV);
        const int er = lane >> 2;
        const int ec = 2 * (lane & 3);
        const int n = w * 16 + er;
        const float s0 = sinv[n];
        const float s1 = sinv[n + 8];
#pragma unroll
        for (int idx = 0; idx < 32; idx++) {
            const int hf = idx >> 4, rem = idx & 15;
            const int dg = rem >> 1, f = rem & 1;
            const int d = hf * 128 + dg * 16 + f * 8 + ec;
            stg[d * 132 + n]           = accO[idx][0] * s0;
            stg[(d + 1) * 132 + n]     = accO[idx][1] * s0;
            stg[d * 132 + n + 8]       = accO[idx][2] * s1;
            stg[(d + 1) * 132 + n + 8] = accO[idx][3] * s1;
        }
    }
    __syncthreads();

    // ---- epilogue phase 2: coalesced out = stg + x ----
    {
        const float* stg = (const float*)(sm + FA_STG);
        const int dl = tid >> 5;
        const int nn = (tid & 31) * 4;
#pragma unroll 4
        for (int it = 0; it < 32; it++) {
            const int d = it * 8 + dl;
            float4 v = *(const float4*)&stg[d * 132 + nn];
            size_t go = ((size_t)b * CH + d) * N_PIX + n0 + nn;
            float4 xv = *(const float4*)(x + go);
            *(float4*)(out + go) = make_float4(v.x + xv.x, v.y + xv.y,
                                               v.z + xv.z, v.w + xv.w);
        }
    }
}

// ================== launch =========================================================
extern "C" void kernel_launch(void* const* d_in, const int* in_sizes, int n_in,
                              void* d_out, int out_size)
{
    (void)in_sizes; (void)n_in; (void)out_size;
    const float* x  = (const float*)d_in[0];
    const float* Wq = (const float*)d_in[1];
    const float* bq = (const float*)d_in[2];
    const float* Wk = (const float*)d_in[3];
    const float* bk = (const float*)d_in[4];
    const float* Wv = (const float*)d_in[5];
    const float* bv = (const float*)d_in[6];
    float* out = (float*)d_out;

    static int smem_set = 0;
    if (!smem_set) {
        cudaFuncSetAttribute(fused_attn_kernel,
                             cudaFuncAttributeMaxDynamicSharedMemorySize, FA_SMEM);
        smem_set = 1;
    }

    proj_qk_kernel<<<dim3(32, 4), 256>>>(x, Wq, bq, Wk, bk);
    proj_v_kernel<<<dim3(32, 2, 4), 256>>>(x, Wv, bv);
    fused_attn_kernel<<<dim3(32, 1, 4), 256, FA_SMEM>>>(x, out);
}

// round 13
// speedup vs baseline: 3.0167x; 1.1154x over previous
#include <cuda_runtime.h>
#include <cuda_bf16.h>
#include <cuda_fp16.h>
#include <cstdint>

#define N_PIX 4096
#define BATCH 4
#define CH    256
#define DQK   32

typedef unsigned long long u64;
typedef unsigned int u32;

// ---------------- scratch (device globals) ------------------------------------------
__device__ __half g_qf[(size_t)BATCH * N_PIX * DQK];  // Q fp16 [b][n][32]
__device__ __half g_kf[(size_t)BATCH * N_PIX * DQK];  // K fp16 [b][m][32]
__device__ __half g_vf[(size_t)BATCH * CH * N_PIX];   // V fp16 [b][d][m]

// ---------------- f32x2 helpers ------------------------------------------------------
__device__ __forceinline__ u64 fma2(u64 a, u64 b, u64 c) {
    u64 d;
    asm("fma.rn.f32x2 %0, %1, %2, %3;" : "=l"(d) : "l"(a), "l"(b), "l"(c));
    return d;
}
__device__ __forceinline__ u64 pack2(float x, float y) {
    u64 r;
    asm("mov.b64 %0, {%1, %2};" : "=l"(r) : "f"(x), "f"(y));
    return r;
}
__device__ __forceinline__ float2 unpack2(u64 v) {
    float2 r;
    asm("mov.b64 {%0, %1}, %2;" : "=f"(r.x), "=f"(r.y) : "l"(v));
    return r;
}

// ---------------- split-bf16 helper (V projection inputs) ----------------------------
__device__ __forceinline__ void split2(float a, float b, u32& hi, u32& lo) {
    __nv_bfloat162 h = __floats2bfloat162_rn(a, b);
    u32 hraw = *(const u32*)&h;
    float ha = __uint_as_float(hraw << 16);
    float hb = __uint_as_float(hraw & 0xFFFF0000u);
    __nv_bfloat162 l = __floats2bfloat162_rn(a - ha, b - hb);
    hi = hraw;
    lo = *(const u32*)&l;
}

// ---------------- smem / cp.async / mma helpers -------------------------------------
__device__ __forceinline__ u32 smem_u32(const void* p) {
    u32 a;
    asm("{ .reg .u64 t; cvta.to.shared.u64 t, %1; cvt.u32.u64 %0, t; }" : "=r"(a) : "l"(p));
    return a;
}
__device__ __forceinline__ void cp16(u32 d, const void* s) {
    asm volatile("cp.async.cg.shared.global [%0], [%1], 16;" :: "r"(d), "l"(s));
}
#define CP_COMMIT() asm volatile("cp.async.commit_group;" ::: "memory")
#define CP_WAIT2()  asm volatile("cp.async.wait_group 2;" ::: "memory")
#define CP_WAIT1()  asm volatile("cp.async.wait_group 1;" ::: "memory")
#define CP_WAIT0()  asm volatile("cp.async.wait_group 0;" ::: "memory")

__device__ __forceinline__ void ldm4(u32 addr, u32& r0, u32& r1, u32& r2, u32& r3) {
    asm volatile("ldmatrix.sync.aligned.m8n8.x4.shared.b16 {%0,%1,%2,%3}, [%4];"
                 : "=r"(r0), "=r"(r1), "=r"(r2), "=r"(r3) : "r"(addr));
}
__device__ __forceinline__ void ldm4t(u32 addr, u32& r0, u32& r1, u32& r2, u32& r3) {
    asm volatile("ldmatrix.sync.aligned.m8n8.x4.trans.shared.b16 {%0,%1,%2,%3}, [%4];"
                 : "=r"(r0), "=r"(r1), "=r"(r2), "=r"(r3) : "r"(addr));
}
// bf16 MMA (V projection)
__device__ __forceinline__ void mma16816(float* c, const u32* a, u32 b0, u32 b1) {
    asm volatile(
        "mma.sync.aligned.m16n8k16.row.col.f32.bf16.bf16.f32 "
        "{%0,%1,%2,%3}, {%4,%5,%6,%7}, {%8,%9}, {%0,%1,%2,%3};"
        : "+f"(c[0]), "+f"(c[1]), "+f"(c[2]), "+f"(c[3])
        : "r"(a[0]), "r"(a[1]), "r"(a[2]), "r"(a[3]), "r"(b0), "r"(b1));
}
// fp16 MMA (E + PV)
__device__ __forceinline__ void mma16816h(float* c, const u32* a, u32 b0, u32 b1) {
    asm volatile(
        "mma.sync.aligned.m16n8k16.row.col.f32.f16.f16.f32 "
        "{%0,%1,%2,%3}, {%4,%5,%6,%7}, {%8,%9}, {%0,%1,%2,%3};"
        : "+f"(c[0]), "+f"(c[1]), "+f"(c[2]), "+f"(c[3])
        : "r"(a[0]), "r"(a[1]), "r"(a[2]), "r"(a[3]), "r"(b0), "r"(b1));
}
__device__ __forceinline__ u32 ex2h2(u32 z) {
    asm("ex2.approx.f16x2 %0, %0;" : "+r"(z));
    return z;
}

// ================== fat projection kernel ==========================================
// blockIdx.x in [0,32): q/k projection, n0 = x*128 (FFMA2 path, fp16 out)
// blockIdx.x in [32,96): V projection, d0 = ((x-32)>>5)*128, m0 = ((x-32)&31)*128
#define PROJ_SMEM 38400

__global__ void __launch_bounds__(256, 2) proj_fused_kernel(
    const float* __restrict__ x,
    const float* __restrict__ Wq, const float* __restrict__ bq,
    const float* __restrict__ Wk, const float* __restrict__ bk,
    const float* __restrict__ Wv, const float* __restrict__ bv)
{
    extern __shared__ char psm[];
    const int tid = threadIdx.x;
    const int b = blockIdx.y;

    if (blockIdx.x < 32) {
        // ---------------- q/k projection (FFMA2) ----------------
        float* sX = (float*)psm;              // 32 x 132 floats
        float* sW = (float*)(psm + 16896);    // 32 x 68 floats

        const int g = tid & 31;
        const int h = tid >> 5;
        const int n0 = blockIdx.x * 128;
        const bool isq = (h < 4);
        const int dbase = (h & 3) * 8;
        const int woff = (isq ? 0 : 32) + dbase;

        u64 acc[8][2];
#pragma unroll
        for (int i = 0; i < 8; i++) { acc[i][0] = 0; acc[i][1] = 0; }

        for (int c0 = 0; c0 < CH; c0 += 32) {
            __syncthreads();
#pragma unroll
            for (int pass = 0; pass < 4; ++pass) {
                int cc = h + pass * 8;
                const float* src = x + ((size_t)b * CH + c0 + cc) * N_PIX + n0 + g * 4;
                *(float4*)(sX + cc * 132 + g * 4) = *(const float4*)src;
            }
            {
                int d = tid & 31;
                int c4 = (tid >> 5) * 4;
                float4 wq4 = *(const float4*)(Wq + d * CH + c0 + c4);
                float4 wk4 = *(const float4*)(Wk + d * CH + c0 + c4);
                sW[(c4 + 0) * 68 + d] = wq4.x; sW[(c4 + 1) * 68 + d] = wq4.y;
                sW[(c4 + 2) * 68 + d] = wq4.z; sW[(c4 + 3) * 68 + d] = wq4.w;
                sW[(c4 + 0) * 68 + 32 + d] = wk4.x; sW[(c4 + 1) * 68 + 32 + d] = wk4.y;
                sW[(c4 + 2) * 68 + 32 + d] = wk4.z; sW[(c4 + 3) * 68 + 32 + d] = wk4.w;
            }
            __syncthreads();

#pragma unroll 8
            for (int cc = 0; cc < 32; ++cc) {
                float4 xa = *(const float4*)(sX + cc * 132 + g * 4);
                u64 xp0 = pack2(xa.x, xa.y), xp1 = pack2(xa.z, xa.w);
                const float* wp = sW + cc * 68 + woff;
                float4 w0 = *(const float4*)wp;
                float4 w1 = *(const float4*)(wp + 4);
                float wv[8] = {w0.x, w0.y, w0.z, w0.w, w1.x, w1.y, w1.z, w1.w};
#pragma unroll
                for (int i = 0; i < 8; i++) {
                    u64 wd = pack2(wv[i], wv[i]);
                    acc[i][0] = fma2(wd, xp0, acc[i][0]);
                    acc[i][1] = fma2(wd, xp1, acc[i][1]);
                }
            }
        }

        const float* bias = isq ? bq : bk;
        float bb[8];
#pragma unroll
        for (int i = 0; i < 8; i++) bb[i] = bias[dbase + i];
        __half* oq = (isq ? g_qf : g_kf)
                     + ((size_t)b * N_PIX + n0 + g * 4) * DQK + dbase;
#pragma unroll
        for (int j = 0; j < 4; j++) {
            float v[8];
#pragma unroll
            for (int i = 0; i < 8; i++) {
                float2 t = unpack2(acc[i][j >> 1]);
                v[i] = ((j & 1) ? t.y : t.x) + bb[i];
            }
            __half2 p0 = __floats2half2_rn(v[0], v[1]);
            __half2 p1 = __floats2half2_rn(v[2], v[3]);
            __half2 p2 = __floats2half2_rn(v[4], v[5]);
            __half2 p3 = __floats2half2_rn(v[6], v[7]);
            uint4 u = make_uint4(*(const u32*)&p0, *(const u32*)&p1,
                                 *(const u32*)&p2, *(const u32*)&p3);
            *(uint4*)(oq + (size_t)j * DQK) = u;
        }
    } else {
        // ---------------- V projection (tensor cores, split-bf16 inputs) ----------
        __nv_bfloat16* sWh = (__nv_bfloat16*)psm;              // 128 x 40
        __nv_bfloat16* sWl = (__nv_bfloat16*)(psm + 10240);
        __nv_bfloat16* sXh = (__nv_bfloat16*)(psm + 20480);    // 32 x 136
        __nv_bfloat16* sXl = (__nv_bfloat16*)(psm + 29184);

        const int w = tid >> 5, lane = tid & 31;
        const int idx0 = blockIdx.x - 32;
        const int d0 = (idx0 >> 5) * 128;
        const int m0 = (idx0 & 31) * 128;

        float accV[16][4];
#pragma unroll
        for (int i = 0; i < 16; i++)
#pragma unroll
            for (int q = 0; q < 4; q++) accV[i][q] = 0.f;

        const int arow = w * 16 + (lane & 15);
        const int acol = (lane >> 4) << 3;
        const int brow_c = (lane & 7) + ((lane >> 3) & 1) * 8;
        const int bcol_m = ((lane >> 4) & 1) * 8;

        const u32 SWH = smem_u32(sWh), SWL = smem_u32(sWl);
        const u32 SXH = smem_u32(sXh), SXL = smem_u32(sXl);

        for (int c0 = 0; c0 < CH; c0 += 32) {
            __syncthreads();
#pragma unroll
            for (int j = 0; j < 4; j++) {
                int idx = tid + j * 256;
                int d = idx >> 3, c4 = (idx & 7) * 4;
                float4 wv4 = *(const float4*)(Wv + (size_t)(d0 + d) * CH + c0 + c4);
                u32 h0, l0, h1, l1;
                split2(wv4.x, wv4.y, h0, l0);
                split2(wv4.z, wv4.w, h1, l1);
                *(uint2*)&sWh[d * 40 + c4] = make_uint2(h0, h1);
                *(uint2*)&sWl[d * 40 + c4] = make_uint2(l0, l1);
            }
#pragma unroll
            for (int j = 0; j < 4; j++) {
                int idx = tid + j * 256;
                int c = idx >> 5, m4 = (idx & 31) * 4;
                float4 xv4 = *(const float4*)(x + ((size_t)b * CH + c0 + c) * N_PIX + m0 + m4);
                u32 h0, l0, h1, l1;
                split2(xv4.x, xv4.y, h0, l0);
                split2(xv4.z, xv4.w, h1, l1);
                *(uint2*)&sXh[c * 136 + m4] = make_uint2(h0, h1);
                *(uint2*)&sXl[c * 136 + m4] = make_uint2(l0, l1);
            }
            __syncthreads();

#pragma unroll
            for (int kk = 0; kk < 32; kk += 16) {
                u32 ah[4], al[4];
                u32 ao = (u32)(arow * 40 + acol + kk) * 2;
                ldm4(SWH + ao, ah[0], ah[1], ah[2], ah[3]);
                ldm4(SWL + ao, al[0], al[1], al[2], al[3]);
#pragma unroll
                for (int mb = 0; mb < 8; mb++) {
                    u32 boff = (u32)((kk + brow_c) * 136 + mb * 16 + bcol_m) * 2;
                    u32 bh[4], bl[4];
                    ldm4t(SXH + boff, bh[0], bh[1], bh[2], bh[3]);
                    ldm4t(SXL + boff, bl[0], bl[1], bl[2], bl[3]);
                    mma16816(accV[mb * 2],     ah, bh[0], bh[1]);
                    mma16816(accV[mb * 2],     ah, bl[0], bl[1]);
                    mma16816(accV[mb * 2],     al, bh[0], bh[1]);
                    mma16816(accV[mb * 2 + 1], ah, bh[2], bh[3]);
                    mma16816(accV[mb * 2 + 1], ah, bl[2], bl[3]);
                    mma16816(accV[mb * 2 + 1], al, bh[2], bh[3]);
                }
            }
        }

        const int er = lane >> 2, ec = 2 * (lane & 3);
        const int dA = d0 + w * 16 + er;
        const int dB = dA + 8;
        const float biasA = bv[dA], biasB = bv[dB];
#pragma unroll
        for (int mb = 0; mb < 8; mb++) {
#pragma unroll
            for (int hf = 0; hf < 2; hf++) {
                const float* c = accV[mb * 2 + hf];
                int m = m0 + mb * 16 + hf * 8 + ec;
                __half2 vA = __floats2half2_rn(c[0] + biasA, c[1] + biasA);
                __half2 vB = __floats2half2_rn(c[2] + biasB, c[3] + biasB);
                *(u32*)&g_vf[((size_t)b * CH + dA) * N_PIX + m] = *(const u32*)&vA;
                *(u32*)&g_vf[((size_t)b * CH + dB) * N_PIX + m] = *(const u32*)&vB;
            }
        }
    }
}

// ================== fused attention: fp16 E + fp16 PV + online max =================
#define FA_Q    0u           // 128 x 40 halves (10240 B)
#define FA_K    10240u       // 2 stages x 10240 B
#define FA_KBUF 10240u
#define FA_V0   30720u       // 128 x 136 halves (34816 B)
#define FA_V1   65536u
#define FA_STG  0u           // epilogue staging: 256 x 132 floats (135168 B)
#define FA_SROW 135168u
#define FA_SINV 135680u
#define FA_SMEM 136192u

__global__ void __launch_bounds__(256, 1) fused_attn_kernel(
    const float* __restrict__ x, float* __restrict__ out)
{
    extern __shared__ char sm[];
    const u32 S = smem_u32(sm);

    const int tid = threadIdx.x;
    const int w = tid >> 5, lane = tid & 31;
    const int b  = blockIdx.z;
    const int n0 = blockIdx.x * 128;

    const __half* qf = g_qf + ((size_t)b * N_PIX + n0) * DQK;
    const __half* kf = g_kf + (size_t)b * N_PIX * DQK;
    const __half* vf = g_vf + (size_t)b * CH * N_PIX;

    auto load_q = [&]() {
#pragma unroll
        for (int j = 0; j < 2; ++j) {
            int idx = tid + j * 256;          // 0..511
            int row = idx >> 2, c = idx & 3;
            cp16(S + FA_Q + (u32)(row * 40 + c * 8) * 2, qf + (size_t)row * DQK + c * 8);
        }
    };
    auto load_k = [&](int t2, u32 kbuf) {
#pragma unroll
        for (int j = 0; j < 2; ++j) {
            int idx = tid + j * 256;
            int row = idx >> 2, c = idx & 3;
            cp16(kbuf + (u32)(row * 40 + c * 8) * 2,
                 kf + ((size_t)t2 * 128 + row) * DQK + c * 8);
        }
    };
    auto load_v = [&](int m0, int hf) {
        const u32 vb = S + (hf ? FA_V1 : FA_V0);
#pragma unroll
        for (int j = 0; j < 8; ++j) {
            int idx = tid + j * 256;
            int row = idx >> 4, c = idx & 15;
            const __half* src = vf + ((size_t)(hf * 128 + row)) * N_PIX + m0 + c * 8;
            cp16(vb + (u32)(row * 136 + c * 8) * 2, src);
        }
    };

    // ---- prologue: G1 = Q + K(0); G2 = V(0,h0); G3 = V(0,h1) + K(1) ----
    load_q(); load_k(0, S + FA_K); CP_COMMIT();
    load_v(0, 0); CP_COMMIT();
    load_v(0, 1); load_k(1, S + FA_K + FA_KBUF); CP_COMMIT();

    float accO[32][4];
#pragma unroll
    for (int i = 0; i < 32; i++)
#pragma unroll
        for (int q = 0; q < 4; q++) accO[i][q] = 0.f;
    float accRS[4] = {0.f, 0.f, 0.f, 0.f};
    float M0 = -1e30f, M1 = -1e30f;

    const int arow = w * 16 + (lane & 15);
    const int acol = (lane >> 4) << 3;
    const int brow = (lane & 7) + ((lane >> 4) & 1) * 8;
    const int bcol = ((lane >> 3) & 1) * 8;
    const u32 ONESH2 = 0x3C003C00u;
    const float L2E = 1.4426950408889634f;

    const int NT = N_PIX / 128;
    for (int t = 0; t < NT; ++t) {
        CP_WAIT2();
        __syncthreads();

        // ---- E phase: fp16 single-term ----
        const u32 kb = S + FA_K + (u32)(t & 1) * FA_KBUF;
        float accE[16][4];
#pragma unroll
        for (int i = 0; i < 16; i++)
#pragma unroll
            for (int q = 0; q < 4; q++) accE[i][q] = 0.f;

#pragma unroll
        for (int kk = 0; kk < 32; kk += 16) {
            u32 a4[4];
            u32 ao = (u32)(arow * 40 + acol + kk) * 2;
            ldm4(S + FA_Q + ao, a4[0], a4[1], a4[2], a4[3]);
#pragma unroll
            for (int nf = 0; nf < 8; nf++) {
                u32 bo = (u32)((nf * 16 + brow) * 40 + bcol + kk) * 2;
                u32 b0, b1, b2, b3;
                ldm4(kb + bo, b0, b1, b2, b3);
                mma16816h(accE[nf * 2],     a4, b0, b1);
                mma16816h(accE[nf * 2 + 1], a4, b2, b3);
            }
        }

        // ---- online max + guarded rescale ----
        float tm0 = -1e30f, tm1 = -1e30f;
#pragma unroll
        for (int i = 0; i < 16; i++) {
            tm0 = fmaxf(tm0, fmaxf(accE[i][0], accE[i][1]));
            tm1 = fmaxf(tm1, fmaxf(accE[i][2], accE[i][3]));
        }
        tm0 = fmaxf(tm0, __shfl_xor_sync(0xffffffffu, tm0, 1));
        tm0 = fmaxf(tm0, __shfl_xor_sync(0xffffffffu, tm0, 2));
        tm1 = fmaxf(tm1, __shfl_xor_sync(0xffffffffu, tm1, 1));
        tm1 = fmaxf(tm1, __shfl_xor_sync(0xffffffffu, tm1, 2));
        float nM0 = fmaxf(M0, tm0), nM1 = fmaxf(M1, tm1);
        if (__any_sync(0xffffffffu, (nM0 > M0) || (nM1 > M1))) {
            float sc0 = __expf(M0 - nM0), sc1 = __expf(M1 - nM1);
#pragma unroll
            for (int i = 0; i < 32; i++) {
                accO[i][0] *= sc0; accO[i][1] *= sc0;
                accO[i][2] *= sc1; accO[i][3] *= sc1;
            }
            accRS[0] *= sc0; accRS[2] *= sc1;
        }
        M0 = nM0; M1 = nM1;

        // ---- exp via ex2.approx.f16x2, P frags in fp16 regs ----
        u32 pa[8][4];
        const float zb0 = -M0 * L2E, zb1 = -M1 * L2E;
#pragma unroll
        for (int ks = 0; ks < 8; ks++) {
            float z00 = fmaf(accE[2 * ks][0], L2E, zb0);
            float z01 = fmaf(accE[2 * ks][1], L2E, zb0);
            float z02 = fmaf(accE[2 * ks][2], L2E, zb1);
            float z03 = fmaf(accE[2 * ks][3], L2E, zb1);
            float z10 = fmaf(accE[2 * ks + 1][0], L2E, zb0);
            float z11 = fmaf(accE[2 * ks + 1][1], L2E, zb0);
            float z12 = fmaf(accE[2 * ks + 1][2], L2E, zb1);
            float z13 = fmaf(accE[2 * ks + 1][3], L2E, zb1);
            __half2 h0 = __floats2half2_rn(z00, z01);
            __half2 h1 = __floats2half2_rn(z02, z03);
            __half2 h2 = __floats2half2_rn(z10, z11);
            __half2 h3 = __floats2half2_rn(z12, z13);
            pa[ks][0] = ex2h2(*(const u32*)&h0);
            pa[ks][1] = ex2h2(*(const u32*)&h1);
            pa[ks][2] = ex2h2(*(const u32*)&h2);
            pa[ks][3] = ex2h2(*(const u32*)&h3);
        }
#pragma unroll
        for (int ks = 0; ks < 8; ks++)
            mma16816h(accRS, pa[ks], ONESH2, ONESH2);

        // ---- PV half 0 (d 0..127) ----
        CP_WAIT1();
        __syncthreads();
        {
            const u32 vb = S + FA_V0;
#pragma unroll
            for (int ks = 0; ks < 8; ks++) {
#pragma unroll
                for (int dg = 0; dg < 8; dg++) {
                    u32 boff = (u32)((dg * 16 + brow) * 136 + bcol + ks * 16) * 2;
                    u32 b0, b1, b2, b3;
                    ldm4(vb + boff, b0, b1, b2, b3);
                    mma16816h(accO[dg * 2],     pa[ks], b0, b1);
                    mma16816h(accO[dg * 2 + 1], pa[ks], b2, b3);
                }
            }
        }
        __syncthreads();
        {
            int tv = (t + 1 < NT) ? t + 1 : NT - 1;
            load_v(tv * 128, 0);
            CP_COMMIT();
        }

        // ---- PV half 1 (d 128..255) ----
        CP_WAIT1();
        __syncthreads();
        {
            const u32 vb = S + FA_V1;
#pragma unroll
            for (int ks = 0; ks < 8; ks++) {
#pragma unroll
                for (int dg = 0; dg < 8; dg++) {
                    u32 boff = (u32)((dg * 16 + brow) * 136 + bcol + ks * 16) * 2;
                    u32 b0, b1, b2, b3;
                    ldm4(vb + boff, b0, b1, b2, b3);
                    mma16816h(accO[16 + dg * 2],     pa[ks], b0, b1);
                    mma16816h(accO[16 + dg * 2 + 1], pa[ks], b2, b3);
                }
            }
        }
        __syncthreads();
        {
            int tv = (t + 1 < NT) ? t + 1 : NT - 1;
            int tk = (t + 2 < NT) ? t + 2 : NT - 1;
            load_v(tv * 128, 1);
            load_k(tk, S + FA_K + (u32)(t & 1) * FA_KBUF);
            CP_COMMIT();
        }
    }

    CP_WAIT0();
    __syncthreads();

    // ---- row sums -> 1/sum ----
    if ((lane & 3) == 0) {
        ((float*)(sm + FA_SROW))[w * 16 + (lane >> 2)] = accRS[0];
        ((float*)(sm + FA_SROW))[w * 16 + (lane >> 2) + 8] = accRS[2];
    }
    __syncthreads();
    if (tid < 128)
        ((float*)(sm + FA_SINV))[tid] = 1.0f / ((float*)(sm + FA_SROW))[tid];
    __syncthreads();

    // ---- epilogue phase 1: O^T regs -> staging smem [d][n], scaled by rinv[n] ----
    {
        float* stg = (float*)(sm + FA_STG);
        const float* sinv = (const float*)(sm + FA_SINV);
        const int er = lane >> 2;
        const int ec = 2 * (lane & 3);
        const int n = w * 16 + er;
        const float s0 = sinv[n];
        const float s1 = sinv[n + 8];
#pragma unroll
        for (int idx = 0; idx < 32; idx++) {
            const int hf = idx >> 4, rem = idx & 15;
            const int dg = rem >> 1, f = rem & 1;
            const int d = hf * 128 + dg * 16 + f * 8 + ec;
            stg[d * 132 + n]           = accO[idx][0] * s0;
            stg[(d + 1) * 132 + n]     = accO[idx][1] * s0;
            stg[d * 132 + n + 8]       = accO[idx][2] * s1;
            stg[(d + 1) * 132 + n + 8] = accO[idx][3] * s1;
        }
    }
    __syncthreads();

    // ---- epilogue phase 2: coalesced out = stg + x ----
    {
        const float* stg = (const float*)(sm + FA_STG);
        const int dl = tid >> 5;
        const int nn = (tid & 31) * 4;
#pragma unroll 4
        for (int it = 0; it < 32; it++) {
            const int d = it * 8 + dl;
            float4 v = *(const float4*)&stg[d * 132 + nn];
            size_t go = ((size_t)b * CH + d) * N_PIX + n0 + nn;
            float4 xv = *(const float4*)(x + go);
            *(float4*)(out + go) = make_float4(v.x + xv.x, v.y + xv.y,
                                               v.z + xv.z, v.w + xv.w);
        }
    }
}

// ================== launch =========================================================
extern "C" void kernel_launch(void* const* d_in, const int* in_sizes, int n_in,
                              void* d_out, int out_size)
{
    (void)in_sizes; (void)n_in; (void)out_size;
    const float* x  = (const float*)d_in[0];
    const float* Wq = (const float*)d_in[1];
    const float* bq = (const float*)d_in[2];
    const float* Wk = (const float*)d_in[3];
    const float* bk = (const float*)d_in[4];
    const float* Wv = (const float*)d_in[5];
    const float* bv = (const float*)d_in[6];
    float* out = (float*)d_out;

    static int smem_set = 0;
    if (!smem_set) {
        cudaFuncSetAttribute(fused_attn_kernel,
                             cudaFuncAttributeMaxDynamicSharedMemorySize, FA_SMEM);
        cudaFuncSetAttribute(proj_fused_kernel,
                             cudaFuncAttributeMaxDynamicSharedMemorySize, PROJ_SMEM);
        smem_set = 1;
    }

    proj_fused_kernel<<<dim3(96, 4), 256, PROJ_SMEM>>>(x, Wq, bq, Wk, bk, Wv, bv);
    fused_attn_kernel<<<dim3(32, 1, 4), 256, FA_SMEM>>>(x, out);
}